// round 2
// baseline (speedup 1.0000x reference)
#include <cuda_runtime.h>
#include <cuda_bf16.h>
#include <math.h>

// Problem constants
#define Bn 4
#define FC 64
#define TC 64
#define HID 48
#define HR 2
#define Gg 8
#define Hc 128
#define Wc 256
#define Dd 5
#define CG 8
#define GRU_IN 236
#define HW (Hc*Wc)            // 32768
#define NPIX (Bn*HW)          // 131072

// Output layout (flattened tuple in return order)
#define O_D    0
#define O_SX   (NPIX)
#define O_SY   (2*NPIX)
#define O_H    (3*NPIX)
#define O_CONF (3*NPIX + Bn*TC*HW)

// Scratch (device globals; no allocation allowed)
__device__ float g_hctx[(size_t)Bn*GRU_IN*HW];   // 236-channel GRU input
__device__ float g_z  [(size_t)Bn*TC*HW];
__device__ float g_r  [(size_t)Bn*TC*HW];        // becomes r*feat after mul
__device__ float g_hnew[(size_t)Bn*TC*HW];
__device__ float g_ta [(size_t)Bn*HID*HW];
__device__ float g_tb [(size_t)Bn*HID*HW];
__device__ float g_gn [128];                     // 2 sets x 32 groups x (mean,rstd)

__device__ __forceinline__ float sigmoidf_(float x){ return 1.0f/(1.0f+expf(-x)); }

// ---------------------------------------------------------------------------
// K1: build hctx = [feat(64), fL(64), fR_w(64), d, sx, sy, conf, cost(40)]
// ---------------------------------------------------------------------------
__global__ void build_hctx_k(const float* __restrict__ d_, const float* __restrict__ sx,
                             const float* __restrict__ sy, const float* __restrict__ conf,
                             const float* __restrict__ feat, const float* __restrict__ fL,
                             const float* __restrict__ fR)
{
    int idx = blockIdx.x*blockDim.x + threadIdx.x;
    if (idx >= NPIX) return;
    int w = idx & (Wc-1);
    int h = (idx >> 8) & (Hc-1);
    int b = idx >> 15;
    size_t p = (size_t)h*Wc + w;        // within-plane index
    size_t pix = (size_t)idx;           // [B,1,H,W] index

    float d0 = d_[pix];

    int i0[Dd], i1[Dd]; float fr[Dd];
#pragma unroll
    for (int o = 0; o < Dd; o++) {
        float xs = (float)w - d0 - (float)(o - HR);
        xs = fminf(fmaxf(xs, 0.0f), (float)(Wc-1));
        float x0f = floorf(xs);
        i0[o] = (int)x0f;
        i1[o] = min(i0[o] + 1, Wc-1);
        fr[o] = xs - x0f;
    }

    size_t hb = (size_t)b * GRU_IN * HW;
    float cost[Dd] = {0.f,0.f,0.f,0.f,0.f};

    for (int c = 0; c < FC; c++) {
        size_t fbase = ((size_t)(b*FC + c)) * HW;
        float fl = fL[fbase + p];
        g_hctx[hb + (size_t)(64 + c)*HW + p] = fl;
        g_hctx[hb + (size_t)c*HW + p]        = feat[fbase + p];
        const float* fRrow = fR + fbase + (size_t)h*Wc;
#pragma unroll
        for (int o = 0; o < Dd; o++) {
            float s = fRrow[i0[o]]*(1.0f-fr[o]) + fRrow[i1[o]]*fr[o];
            cost[o] += fl * s;
            if (o == HR) g_hctx[hb + (size_t)(128 + c)*HW + p] = s;  // fR_w (off=0)
        }
        if ((c & (CG-1)) == (CG-1)) {
            int g = c >> 3;
#pragma unroll
            for (int o = 0; o < Dd; o++) {
                g_hctx[hb + (size_t)(196 + g*Dd + o)*HW + p] = cost[o] * (1.0f/(float)CG);
                cost[o] = 0.f;
            }
        }
    }
    g_hctx[hb + (size_t)192*HW + p] = d0;
    g_hctx[hb + (size_t)193*HW + p] = sx[pix];
    g_hctx[hb + (size_t)194*HW + p] = sy[pix];
    g_hctx[hb + (size_t)195*HW + p] = conf[pix];
}

// ---------------------------------------------------------------------------
// Generic 3x3 conv (pad=1), input may be split across two tensors.
// MODE 0: none, 1: sigmoid, 2: GRU (tanh + h_new combine, dual write)
// Block: 256 threads = 32 lanes x 8 oc-groups; tile = 128 pixels of one row.
// ---------------------------------------------------------------------------
template<int IC, int OC, int MODE>
__global__ void __launch_bounds__(256)
conv3x3_k(const float* __restrict__ inA, int CAtot, int A0, int CA,
          const float* __restrict__ inB, int CBtot, int B0,
          const float* __restrict__ wgt, const float* __restrict__ bias,
          float* __restrict__ out,
          const float* __restrict__ zbuf, const float* __restrict__ featbuf,
          float* __restrict__ out2)
{
    constexpr int TW  = 128;
    constexpr int CH  = 4;          // channels staged per iteration
    constexpr int OCT = OC / 8;     // ocs per thread

    __shared__ float ism[CH][3][TW+4];
    __shared__ float wsm[CH][OC][9];

    int tid  = threadIdx.x;
    int lane = tid & 31;
    int ocq  = tid >> 5;
    int x0   = blockIdx.x * TW;
    int h    = blockIdx.y;
    int b    = blockIdx.z;

    float acc[OCT][4];
#pragma unroll
    for (int t = 0; t < OCT; t++)
#pragma unroll
        for (int j = 0; j < 4; j++) acc[t][j] = 0.f;

    for (int c0 = 0; c0 < IC; c0 += CH) {
        // stage weights
        for (int idx = tid; idx < CH*OC*9; idx += 256) {
            int cl = idx / (OC*9);
            int r  = idx - cl*(OC*9);
            int oc = r / 9, k = r - oc*9;
            wsm[cl][oc][k] = wgt[((size_t)oc*IC + (c0+cl))*9 + k];
        }
        // stage input rows (h-1..h+1, x0-1..x0+TW)
        for (int idx = tid; idx < CH*3*(TW+2); idx += 256) {
            int cl = idx / (3*(TW+2));
            int r2 = idx - cl*(3*(TW+2));
            int rr = r2 / (TW+2), col = r2 - rr*(TW+2);
            int gy = h - 1 + rr;
            int gx = x0 - 1 + col;
            int c  = c0 + cl;
            float v = 0.f;
            if (gy >= 0 && gy < Hc && gx >= 0 && gx < Wc) {
                const float* pp;
                if (c < CA) pp = inA + (((size_t)b*CAtot + A0 + c)*Hc + gy)*Wc + gx;
                else        pp = inB + (((size_t)b*CBtot + B0 + (c-CA))*Hc + gy)*Wc + gx;
                v = *pp;
            }
            ism[cl][rr][col] = v;
        }
        __syncthreads();

#pragma unroll
        for (int cl = 0; cl < CH; cl++) {
            float v[4][9];
#pragma unroll
            for (int j = 0; j < 4; j++) {
                int px = lane + 32*j;
#pragma unroll
                for (int r = 0; r < 3; r++)
#pragma unroll
                    for (int k = 0; k < 3; k++)
                        v[j][r*3+k] = ism[cl][r][px + k];
            }
#pragma unroll
            for (int t = 0; t < OCT; t++) {
                int oc = ocq*OCT + t;
                float w9[9];
#pragma unroll
                for (int k = 0; k < 9; k++) w9[k] = wsm[cl][oc][k];
#pragma unroll
                for (int j = 0; j < 4; j++) {
                    float s = acc[t][j];
#pragma unroll
                    for (int k = 0; k < 9; k++) s = fmaf(w9[k], v[j][k], s);
                    acc[t][j] = s;
                }
            }
        }
        __syncthreads();
    }

    // epilogue
#pragma unroll
    for (int t = 0; t < OCT; t++) {
        int oc = ocq*OCT + t;
        float bs = bias ? bias[oc] : 0.f;
#pragma unroll
        for (int j = 0; j < 4; j++) {
            int x = x0 + lane + 32*j;
            size_t o = (((size_t)b*OC + oc)*Hc + h)*Wc + x;
            float val = acc[t][j] + bs;
            if (MODE == 0) {
                out[o] = val;
            } else if (MODE == 1) {
                out[o] = sigmoidf_(val);
            } else { // GRU
                float q = tanhf(val);
                float z = zbuf[o];
                float f = featbuf[o];
                float hn = (1.0f - z)*f + z*q;
                out[o]  = hn;
                out2[o] = hn;
            }
        }
    }
}

// ---------------------------------------------------------------------------
// r <- r * feat (elementwise)
// ---------------------------------------------------------------------------
__global__ void mul_k(float* __restrict__ r, const float* __restrict__ feat, int n)
{
    int i = blockIdx.x*blockDim.x + threadIdx.x;
    if (i < n) r[i] = r[i] * feat[i];
}

// ---------------------------------------------------------------------------
// GroupNorm stats: 32 blocks = (b,group); each reduces 6*HW elements
// ---------------------------------------------------------------------------
__global__ void gn_stats_k(const float* __restrict__ x, int set)
{
    __shared__ float ss[256], ss2[256];
    int bg = blockIdx.x;            // b*8 + g
    int b  = bg >> 3, g = bg & 7;
    size_t base = ((size_t)b*HID + g*(HID/Gg)) * HW;
    const int N = (HID/Gg) * HW;    // 196608
    float s = 0.f, s2 = 0.f;
    for (int i = threadIdx.x; i < N; i += 256) {
        float v = x[base + i];
        s += v; s2 += v*v;
    }
    ss[threadIdx.x] = s; ss2[threadIdx.x] = s2;
    __syncthreads();
    for (int off = 128; off > 0; off >>= 1) {
        if (threadIdx.x < off) {
            ss[threadIdx.x]  += ss[threadIdx.x + off];
            ss2[threadIdx.x] += ss2[threadIdx.x + off];
        }
        __syncthreads();
    }
    if (threadIdx.x == 0) {
        float mean = ss[0] / (float)N;
        float var  = ss2[0] / (float)N - mean*mean;
        g_gn[set*64 + bg*2]     = mean;
        g_gn[set*64 + bg*2 + 1] = rsqrtf(var + 1e-5f);
    }
}

// ---------------------------------------------------------------------------
// GroupNorm apply + SiLU
// ---------------------------------------------------------------------------
__global__ void gn_apply_k(const float* __restrict__ x, float* __restrict__ y,
                           const float* __restrict__ scale, const float* __restrict__ bias,
                           int set)
{
    int i = blockIdx.x*blockDim.x + threadIdx.x;
    const int n = Bn*HID*HW;
    if (i >= n) return;
    int c = (i / HW) % HID;
    int b = i / (HID*HW);
    int grp = c / (HID/Gg);
    float mean = g_gn[set*64 + (b*8+grp)*2];
    float rstd = g_gn[set*64 + (b*8+grp)*2 + 1];
    float v = (x[i] - mean)*rstd*scale[c] + bias[c];
    y[i] = v * sigmoidf_(v);
}

// ---------------------------------------------------------------------------
// Heads: four 1x1 convs (48->1) + activations; writes d/sx/sy/conf outputs
// ---------------------------------------------------------------------------
__global__ void heads_k(const float* __restrict__ t,
                        const float* __restrict__ d_, const float* __restrict__ sx,
                        const float* __restrict__ sy, const float* __restrict__ conf,
                        const float* __restrict__ wd,  const float* __restrict__ bd,
                        const float* __restrict__ wsx, const float* __restrict__ bsx,
                        const float* __restrict__ wsy, const float* __restrict__ bsy,
                        const float* __restrict__ wcf, const float* __restrict__ bcf,
                        float* __restrict__ out)
{
    __shared__ float wsm[4][HID];
    int tid = threadIdx.x;
    if (tid < HID)              wsm[0][tid]        = wd [tid];
    else if (tid < 2*HID)       wsm[1][tid-HID]    = wsx[tid-HID];
    else if (tid < 3*HID)       wsm[2][tid-2*HID]  = wsy[tid-2*HID];
    else if (tid < 4*HID)       wsm[3][tid-3*HID]  = wcf[tid-3*HID];
    __syncthreads();

    int idx = blockIdx.x*blockDim.x + tid;
    if (idx >= NPIX) return;
    int b = idx >> 15;
    size_t p = (size_t)(idx & (HW-1));
    size_t pix = (size_t)idx;

    float a0=0.f, a1=0.f, a2=0.f, a3=0.f;
    size_t base = (size_t)b*HID*HW + p;
    for (int c = 0; c < HID; c++) {
        float v = t[base + (size_t)c*HW];
        a0 = fmaf(v, wsm[0][c], a0);
        a1 = fmaf(v, wsm[1][c], a1);
        a2 = fmaf(v, wsm[2][c], a2);
        a3 = fmaf(v, wsm[3][c], a3);
    }
    // d_out = softplus(conv + d)
    float ad = a0 + bd[0] + d_[pix];
    out[O_D + pix]  = (ad > 20.0f) ? ad : log1pf(expf(ad));
    out[O_SX + pix] = sx[pix] + (a1 + bsx[0]) * 0.1f;
    out[O_SY + pix] = sy[pix] + (a2 + bsy[0]) * 0.1f;
    out[O_CONF + pix] = sigmoidf_(a3 + bcf[0] + 2.0f*conf[pix] - 1.0f);
}

// ---------------------------------------------------------------------------
extern "C" void kernel_launch(void* const* d_in, const int* in_sizes, int n_in,
                              void* d_out, int out_size)
{
    const float* d_   = (const float*)d_in[0];
    const float* sx   = (const float*)d_in[1];
    const float* sy   = (const float*)d_in[2];
    const float* conf = (const float*)d_in[3];
    const float* feat = (const float*)d_in[4];
    const float* fL   = (const float*)d_in[5];
    const float* fR   = (const float*)d_in[6];
    const float* wz   = (const float*)d_in[7];
    const float* bz   = (const float*)d_in[8];
    const float* wr   = (const float*)d_in[9];
    const float* br   = (const float*)d_in[10];
    const float* wq   = (const float*)d_in[11];
    const float* bq   = (const float*)d_in[12];
    const float* w1   = (const float*)d_in[13];
    const float* g1s  = (const float*)d_in[14];
    const float* g1b  = (const float*)d_in[15];
    const float* w2   = (const float*)d_in[16];
    const float* g2s  = (const float*)d_in[17];
    const float* g2b  = (const float*)d_in[18];
    const float* whd  = (const float*)d_in[19];
    const float* bhd  = (const float*)d_in[20];
    const float* whx  = (const float*)d_in[21];
    const float* bhx  = (const float*)d_in[22];
    const float* why  = (const float*)d_in[23];
    const float* bhy  = (const float*)d_in[24];
    const float* whc  = (const float*)d_in[25];
    const float* bhc  = (const float*)d_in[26];
    float* out = (float*)d_out;

    float *hctx, *z, *r, *hnew, *ta, *tb;
    cudaGetSymbolAddress((void**)&hctx, g_hctx);
    cudaGetSymbolAddress((void**)&z,    g_z);
    cudaGetSymbolAddress((void**)&r,    g_r);
    cudaGetSymbolAddress((void**)&hnew, g_hnew);
    cudaGetSymbolAddress((void**)&ta,   g_ta);
    cudaGetSymbolAddress((void**)&tb,   g_tb);

    dim3 cgrid(Wc/128, Hc, Bn);

    build_hctx_k<<<NPIX/256, 256>>>(d_, sx, sy, conf, feat, fL, fR);

    conv3x3_k<GRU_IN, TC, 1><<<cgrid, 256>>>(hctx, GRU_IN, 0, GRU_IN,
                                             nullptr, 0, 0, wz, bz, z,
                                             nullptr, nullptr, nullptr);
    conv3x3_k<GRU_IN, TC, 1><<<cgrid, 256>>>(hctx, GRU_IN, 0, GRU_IN,
                                             nullptr, 0, 0, wr, br, r,
                                             nullptr, nullptr, nullptr);
    mul_k<<<(Bn*TC*HW)/256, 256>>>(r, feat, Bn*TC*HW);

    conv3x3_k<GRU_IN, TC, 2><<<cgrid, 256>>>(r, TC, 0, TC,
                                             hctx, GRU_IN, 64, wq, bq, hnew,
                                             z, feat, out + O_H);

    conv3x3_k<TC, HID, 0><<<cgrid, 256>>>(hnew, TC, 0, TC,
                                          nullptr, 0, 0, w1, nullptr, ta,
                                          nullptr, nullptr, nullptr);
    gn_stats_k<<<32, 256>>>(ta, 0);
    gn_apply_k<<<(Bn*HID*HW)/256, 256>>>(ta, tb, g1s, g1b, 0);

    conv3x3_k<HID, HID, 0><<<cgrid, 256>>>(tb, HID, 0, HID,
                                           nullptr, 0, 0, w2, nullptr, ta,
                                           nullptr, nullptr, nullptr);
    gn_stats_k<<<32, 256>>>(ta, 1);
    gn_apply_k<<<(Bn*HID*HW)/256, 256>>>(ta, tb, g2s, g2b, 1);

    heads_k<<<NPIX/256, 256>>>(tb, d_, sx, sy, conf,
                               whd, bhd, whx, bhx, why, bhy, whc, bhc, out);
}

// round 3
// speedup vs baseline: 1.7328x; 1.7328x over previous
#include <cuda_runtime.h>
#include <cuda_bf16.h>
#include <math.h>

// Problem constants
#define Bn 4
#define FC 64
#define TC 64
#define HID 48
#define HR 2
#define Gg 8
#define Hc 128
#define Wc 256
#define Dd 5
#define CG 8
#define GRU_IN 236
#define HW (Hc*Wc)            // 32768
#define NPIX (Bn*HW)          // 131072

// Output layout (flattened tuple in return order)
#define O_D    0
#define O_SX   (NPIX)
#define O_SY   (2*NPIX)
#define O_H    (3*NPIX)
#define O_CONF (3*NPIX + Bn*TC*HW)

// Scratch (device globals; no allocation allowed)
__device__ float g_hctx[(size_t)Bn*GRU_IN*HW];   // 236-channel GRU input
__device__ float g_z  [(size_t)Bn*TC*HW];
__device__ float g_r  [(size_t)Bn*TC*HW];        // holds r*feat (fused)
__device__ float g_hnew[(size_t)Bn*TC*HW];
__device__ float g_ta [(size_t)Bn*HID*HW];
__device__ float g_tb [(size_t)Bn*HID*HW];
__device__ float g_gn [128];                     // 2 sets x 32 groups x (mean,rstd)

__device__ __forceinline__ float sigmoidf_(float x){ return 1.0f/(1.0f+expf(-x)); }

__device__ __forceinline__ unsigned to_tf32(float v) {
    unsigned u;
    asm("cvt.rna.tf32.f32 %0, %1;" : "=r"(u) : "f"(v));
    return u;
}

__device__ __forceinline__ void mma_tf32(float* c, unsigned a0, unsigned a1,
                                         unsigned a2, unsigned a3,
                                         unsigned b0, unsigned b1) {
    asm volatile(
        "mma.sync.aligned.m16n8k8.row.col.f32.tf32.tf32.f32 "
        "{%0,%1,%2,%3}, {%4,%5,%6,%7}, {%8,%9}, {%0,%1,%2,%3};"
        : "+f"(c[0]), "+f"(c[1]), "+f"(c[2]), "+f"(c[3])
        : "r"(a0), "r"(a1), "r"(a2), "r"(a3), "r"(b0), "r"(b1));
}

// ---------------------------------------------------------------------------
// K1: build hctx = [feat(64), fL(64), fR_w(64), d, sx, sy, conf, cost(40)]
// ---------------------------------------------------------------------------
__global__ void build_hctx_k(const float* __restrict__ d_, const float* __restrict__ sx,
                             const float* __restrict__ sy, const float* __restrict__ conf,
                             const float* __restrict__ feat, const float* __restrict__ fL,
                             const float* __restrict__ fR)
{
    int idx = blockIdx.x*blockDim.x + threadIdx.x;
    if (idx >= NPIX) return;
    int w = idx & (Wc-1);
    int h = (idx >> 8) & (Hc-1);
    int b = idx >> 15;
    size_t p = (size_t)h*Wc + w;
    size_t pix = (size_t)idx;

    float d0 = d_[pix];

    int i0[Dd], i1[Dd]; float fr[Dd];
#pragma unroll
    for (int o = 0; o < Dd; o++) {
        float xs = (float)w - d0 - (float)(o - HR);
        xs = fminf(fmaxf(xs, 0.0f), (float)(Wc-1));
        float x0f = floorf(xs);
        i0[o] = (int)x0f;
        i1[o] = min(i0[o] + 1, Wc-1);
        fr[o] = xs - x0f;
    }

    size_t hb = (size_t)b * GRU_IN * HW;
    float cost[Dd] = {0.f,0.f,0.f,0.f,0.f};

    for (int c = 0; c < FC; c++) {
        size_t fbase = ((size_t)(b*FC + c)) * HW;
        float fl = fL[fbase + p];
        g_hctx[hb + (size_t)(64 + c)*HW + p] = fl;
        g_hctx[hb + (size_t)c*HW + p]        = feat[fbase + p];
        const float* fRrow = fR + fbase + (size_t)h*Wc;
#pragma unroll
        for (int o = 0; o < Dd; o++) {
            float s = fRrow[i0[o]]*(1.0f-fr[o]) + fRrow[i1[o]]*fr[o];
            cost[o] += fl * s;
            if (o == HR) g_hctx[hb + (size_t)(128 + c)*HW + p] = s;
        }
        if ((c & (CG-1)) == (CG-1)) {
            int g = c >> 3;
#pragma unroll
            for (int o = 0; o < Dd; o++) {
                g_hctx[hb + (size_t)(196 + g*Dd + o)*HW + p] = cost[o] * (1.0f/(float)CG);
                cost[o] = 0.f;
            }
        }
    }
    g_hctx[hb + (size_t)192*HW + p] = d0;
    g_hctx[hb + (size_t)193*HW + p] = sx[pix];
    g_hctx[hb + (size_t)194*HW + p] = sy[pix];
    g_hctx[hb + (size_t)195*HW + p] = conf[pix];
}

// ---------------------------------------------------------------------------
// Tensor-core 3x3 conv (pad=1) via implicit GEMM, mma.sync m16n8k8 tf32.
// CTA tile = one full row (256 px) x OC channels. 8 warps: 4 (px) x 2 (oc).
// Each warp: 64 px x OC/2 oc. K = IC*9 processed as 8-ic chunks x 9 taps.
// MODE 0: none, 1: sigmoid, 2: GRU combine, 3: sigmoid * featbuf
// Input may be split across two tensors (first CA channels from inA at A0,
// remainder from inB at B0).
// ---------------------------------------------------------------------------
template<int IC, int OC, int MODE>
__global__ void __launch_bounds__(256, 2)
conv3x3_mma_k(const float* __restrict__ inA, int CAtot, int A0, int CA,
              const float* __restrict__ inB, int CBtot, int B0,
              const float* __restrict__ wgt, const float* __restrict__ bias,
              float* __restrict__ out,
              const float* __restrict__ zbuf, const float* __restrict__ featbuf,
              float* __restrict__ out2)
{
    constexpr int CH   = 8;            // ics per chunk
    constexpr int P    = 264;          // ism col pitch (words)
    constexpr int OCP  = 72;           // wsm oc pitch (words)
    constexpr int NCHK = (IC + CH - 1) / CH;
    constexpr int OCW  = OC / 2;       // oc per warp
    constexpr int NF   = OCW / 8;      // n-fragments per warp

    __shared__ unsigned ism[CH*3*P];       // [icl][ky][c], c = x+1 (halo)
    __shared__ unsigned wsm[9*CH*OCP];     // [tap][icl][oc]

    const int tid  = threadIdx.x;
    const int lane = tid & 31;
    const int warp = tid >> 5;
    const int wm   = warp & 3;             // pixel quadrant (64 px each)
    const int wn   = warp >> 2;            // oc half
    const int h    = blockIdx.x;
    const int b    = blockIdx.y;
    const int gID  = lane >> 2;            // group id
    const int tig  = lane & 3;             // thread in group

    float acc[4][NF][4];
#pragma unroll
    for (int mf = 0; mf < 4; mf++)
#pragma unroll
        for (int f = 0; f < NF; f++)
#pragma unroll
            for (int j = 0; j < 4; j++) acc[mf][f][j] = 0.f;

    for (int chunk = 0; chunk < NCHK; chunk++) {
        // ---- stage input slab: CH ics x 3 rows x 258 cols (tf32-rounded)
        for (int i = tid; i < CH*3*258; i += 256) {
            int icl = i / (3*258);
            int r   = i - icl*(3*258);
            int ky  = r / 258, c = r - ky*258;
            int gx  = c - 1;
            int gy  = h - 1 + ky;
            int ic  = chunk*CH + icl;
            float v = 0.f;
            if (ic < IC && gy >= 0 && gy < Hc && gx >= 0 && gx < Wc) {
                const float* pp;
                if (ic < CA) pp = inA + (((size_t)b*CAtot + A0 + ic)*Hc + gy)*Wc + gx;
                else         pp = inB + (((size_t)b*CBtot + B0 + (ic-CA))*Hc + gy)*Wc + gx;
                v = *pp;
            }
            ism[icl*3*P + ky*P + c] = to_tf32(v);
        }
        // ---- stage weights: 9 taps x CH ics x OC (coalesced over (tap,icl))
        for (int i = tid; i < CH*9*OC; i += 256) {
            int oc  = i / (CH*9);
            int r   = i - oc*(CH*9);
            int icl = r / 9, tap = r - icl*9;
            int ic  = chunk*CH + icl;
            float v = (ic < IC) ? wgt[((size_t)oc*IC + ic)*9 + tap] : 0.f;
            wsm[tap*CH*OCP + icl*OCP + oc] = to_tf32(v);
        }
        __syncthreads();

#pragma unroll
        for (int tap = 0; tap < 9; tap++) {
            const int ky = tap / 3, kx = tap % 3;
            const unsigned* wbase = &wsm[tap*CH*OCP];
            // B fragments (k = icl, n = oc)
            unsigned b0[NF], b1[NF];
#pragma unroll
            for (int f = 0; f < NF; f++) {
                int oc = wn*OCW + f*8 + gID;
                b0[f] = wbase[ tig     *OCP + oc];
                b1[f] = wbase[(tig + 4)*OCP + oc];
            }
            const unsigned* ibase = &ism[ky*P + kx];
#pragma unroll
            for (int mf = 0; mf < 4; mf++) {
                int p = wm*64 + mf*16 + gID;    // pixel row of a0
                unsigned a0 = ibase[ tig     *3*P + p];
                unsigned a1 = ibase[ tig     *3*P + p + 8];
                unsigned a2 = ibase[(tig + 4)*3*P + p];
                unsigned a3 = ibase[(tig + 4)*3*P + p + 8];
#pragma unroll
                for (int f = 0; f < NF; f++)
                    mma_tf32(acc[mf][f], a0, a1, a2, a3, b0[f], b1[f]);
            }
        }
        __syncthreads();
    }

    // ---- epilogue
#pragma unroll
    for (int mf = 0; mf < 4; mf++) {
#pragma unroll
        for (int f = 0; f < NF; f++) {
            int px0 = wm*64 + mf*16 + gID;
            int oc0 = wn*OCW + f*8 + 2*tig;
#pragma unroll
            for (int e = 0; e < 4; e++) {
                int px = px0 + (e >> 1)*8;
                int oc = oc0 + (e & 1);
                float val = acc[mf][f][e] + (bias ? bias[oc] : 0.f);
                size_t o = (((size_t)b*OC + oc)*Hc + h)*Wc + px;
                if (MODE == 0) {
                    out[o] = val;
                } else if (MODE == 1) {
                    out[o] = sigmoidf_(val);
                } else if (MODE == 3) {
                    out[o] = sigmoidf_(val) * featbuf[o];
                } else { // GRU combine
                    float q = tanhf(val);
                    float z = zbuf[o];
                    float fv = featbuf[o];
                    float hn = (1.0f - z)*fv + z*q;
                    out[o]  = hn;
                    out2[o] = hn;
                }
            }
        }
    }
}

// ---------------------------------------------------------------------------
// GroupNorm stats: 32 blocks = (b,group)
// ---------------------------------------------------------------------------
__global__ void gn_stats_k(const float* __restrict__ x, int set)
{
    __shared__ float ss[256], ss2[256];
    int bg = blockIdx.x;
    int b  = bg >> 3, g = bg & 7;
    size_t base = ((size_t)b*HID + g*(HID/Gg)) * HW;
    const int N = (HID/Gg) * HW;
    float s = 0.f, s2 = 0.f;
    for (int i = threadIdx.x; i < N; i += 256) {
        float v = x[base + i];
        s += v; s2 += v*v;
    }
    ss[threadIdx.x] = s; ss2[threadIdx.x] = s2;
    __syncthreads();
    for (int off = 128; off > 0; off >>= 1) {
        if (threadIdx.x < off) {
            ss[threadIdx.x]  += ss[threadIdx.x + off];
            ss2[threadIdx.x] += ss2[threadIdx.x + off];
        }
        __syncthreads();
    }
    if (threadIdx.x == 0) {
        float mean = ss[0] / (float)N;
        float var  = ss2[0] / (float)N - mean*mean;
        g_gn[set*64 + bg*2]     = mean;
        g_gn[set*64 + bg*2 + 1] = rsqrtf(var + 1e-5f);
    }
}

// ---------------------------------------------------------------------------
// GroupNorm apply + SiLU
// ---------------------------------------------------------------------------
__global__ void gn_apply_k(const float* __restrict__ x, float* __restrict__ y,
                           const float* __restrict__ scale, const float* __restrict__ bias,
                           int set)
{
    int i = blockIdx.x*blockDim.x + threadIdx.x;
    const int n = Bn*HID*HW;
    if (i >= n) return;
    int c = (i / HW) % HID;
    int b = i / (HID*HW);
    int grp = c / (HID/Gg);
    float mean = g_gn[set*64 + (b*8+grp)*2];
    float rstd = g_gn[set*64 + (b*8+grp)*2 + 1];
    float v = (x[i] - mean)*rstd*scale[c] + bias[c];
    y[i] = v * sigmoidf_(v);
}

// ---------------------------------------------------------------------------
// Heads: four 1x1 convs (48->1) + activations
// ---------------------------------------------------------------------------
__global__ void heads_k(const float* __restrict__ t,
                        const float* __restrict__ d_, const float* __restrict__ sx,
                        const float* __restrict__ sy, const float* __restrict__ conf,
                        const float* __restrict__ wd,  const float* __restrict__ bd,
                        const float* __restrict__ wsx, const float* __restrict__ bsx,
                        const float* __restrict__ wsy, const float* __restrict__ bsy,
                        const float* __restrict__ wcf, const float* __restrict__ bcf,
                        float* __restrict__ out)
{
    __shared__ float wsm[4][HID];
    int tid = threadIdx.x;
    if (tid < HID)              wsm[0][tid]        = wd [tid];
    else if (tid < 2*HID)       wsm[1][tid-HID]    = wsx[tid-HID];
    else if (tid < 3*HID)       wsm[2][tid-2*HID]  = wsy[tid-2*HID];
    else if (tid < 4*HID)       wsm[3][tid-3*HID]  = wcf[tid-3*HID];
    __syncthreads();

    int idx = blockIdx.x*blockDim.x + tid;
    if (idx >= NPIX) return;
    int b = idx >> 15;
    size_t p = (size_t)(idx & (HW-1));
    size_t pix = (size_t)idx;

    float a0=0.f, a1=0.f, a2=0.f, a3=0.f;
    size_t base = (size_t)b*HID*HW + p;
    for (int c = 0; c < HID; c++) {
        float v = t[base + (size_t)c*HW];
        a0 = fmaf(v, wsm[0][c], a0);
        a1 = fmaf(v, wsm[1][c], a1);
        a2 = fmaf(v, wsm[2][c], a2);
        a3 = fmaf(v, wsm[3][c], a3);
    }
    float ad = a0 + bd[0] + d_[pix];
    out[O_D + pix]  = (ad > 20.0f) ? ad : log1pf(expf(ad));
    out[O_SX + pix] = sx[pix] + (a1 + bsx[0]) * 0.1f;
    out[O_SY + pix] = sy[pix] + (a2 + bsy[0]) * 0.1f;
    out[O_CONF + pix] = sigmoidf_(a3 + bcf[0] + 2.0f*conf[pix] - 1.0f);
}

// ---------------------------------------------------------------------------
extern "C" void kernel_launch(void* const* d_in, const int* in_sizes, int n_in,
                              void* d_out, int out_size)
{
    const float* d_   = (const float*)d_in[0];
    const float* sx   = (const float*)d_in[1];
    const float* sy   = (const float*)d_in[2];
    const float* conf = (const float*)d_in[3];
    const float* feat = (const float*)d_in[4];
    const float* fL   = (const float*)d_in[5];
    const float* fR   = (const float*)d_in[6];
    const float* wz   = (const float*)d_in[7];
    const float* bz   = (const float*)d_in[8];
    const float* wr   = (const float*)d_in[9];
    const float* br   = (const float*)d_in[10];
    const float* wq   = (const float*)d_in[11];
    const float* bq   = (const float*)d_in[12];
    const float* w1   = (const float*)d_in[13];
    const float* g1s  = (const float*)d_in[14];
    const float* g1b  = (const float*)d_in[15];
    const float* w2   = (const float*)d_in[16];
    const float* g2s  = (const float*)d_in[17];
    const float* g2b  = (const float*)d_in[18];
    const float* whd  = (const float*)d_in[19];
    const float* bhd  = (const float*)d_in[20];
    const float* whx  = (const float*)d_in[21];
    const float* bhx  = (const float*)d_in[22];
    const float* why  = (const float*)d_in[23];
    const float* bhy  = (const float*)d_in[24];
    const float* whc  = (const float*)d_in[25];
    const float* bhc  = (const float*)d_in[26];
    float* out = (float*)d_out;

    float *hctx, *z, *r, *hnew, *ta, *tb;
    cudaGetSymbolAddress((void**)&hctx, g_hctx);
    cudaGetSymbolAddress((void**)&z,    g_z);
    cudaGetSymbolAddress((void**)&r,    g_r);
    cudaGetSymbolAddress((void**)&hnew, g_hnew);
    cudaGetSymbolAddress((void**)&ta,   g_ta);
    cudaGetSymbolAddress((void**)&tb,   g_tb);

    dim3 cgrid(Hc, Bn);

    build_hctx_k<<<NPIX/256, 256>>>(d_, sx, sy, conf, feat, fL, fR);

    // z = sigmoid(conv(hctx))
    conv3x3_mma_k<GRU_IN, TC, 1><<<cgrid, 256>>>(hctx, GRU_IN, 0, GRU_IN,
                                                 nullptr, 0, 0, wz, bz, z,
                                                 nullptr, nullptr, nullptr);
    // r*feat = sigmoid(conv(hctx)) * feat   (fused)
    conv3x3_mma_k<GRU_IN, TC, 3><<<cgrid, 256>>>(hctx, GRU_IN, 0, GRU_IN,
                                                 nullptr, 0, 0, wr, br, r,
                                                 nullptr, feat, nullptr);
    // q-conv + GRU combine -> hnew (and output h slot)
    conv3x3_mma_k<GRU_IN, TC, 2><<<cgrid, 256>>>(r, TC, 0, TC,
                                                 hctx, GRU_IN, 64, wq, bq, hnew,
                                                 z, feat, out + O_H);

    conv3x3_mma_k<TC, HID, 0><<<cgrid, 256>>>(hnew, TC, 0, TC,
                                              nullptr, 0, 0, w1, nullptr, ta,
                                              nullptr, nullptr, nullptr);
    gn_stats_k<<<32, 256>>>(ta, 0);
    gn_apply_k<<<(Bn*HID*HW)/256, 256>>>(ta, tb, g1s, g1b, 0);

    conv3x3_mma_k<HID, HID, 0><<<cgrid, 256>>>(tb, HID, 0, HID,
                                               nullptr, 0, 0, w2, nullptr, ta,
                                               nullptr, nullptr, nullptr);
    gn_stats_k<<<32, 256>>>(ta, 1);
    gn_apply_k<<<(Bn*HID*HW)/256, 256>>>(ta, tb, g2s, g2b, 1);

    heads_k<<<NPIX/256, 256>>>(tb, d_, sx, sy, conf,
                               whd, bhd, whx, bhx, why, bhy, whc, bhc, out);
}

// round 5
// speedup vs baseline: 5.1119x; 2.9501x over previous
#include <cuda_runtime.h>
#include <cuda_bf16.h>
#include <math.h>
#include <stdint.h>

// Problem constants
#define Bn 4
#define FC 64
#define TC 64
#define HID 48
#define HR 2
#define Gg 8
#define Hc 128
#define Wc 256
#define Dd 5
#define CG 8
#define GRU_IN 236
#define HW (Hc*Wc)            // 32768
#define NPIX (Bn*HW)          // 131072

// Output layout (flattened tuple in return order)
#define O_D    0
#define O_SX   (NPIX)
#define O_SY   (2*NPIX)
#define O_H    (3*NPIX)
#define O_CONF (3*NPIX + Bn*TC*HW)

// Scratch (device globals; no allocation allowed)
__device__ float g_hctx[(size_t)Bn*GRU_IN*HW];
__device__ float g_z  [(size_t)Bn*TC*HW];
__device__ float g_r  [(size_t)Bn*TC*HW];        // holds r*feat (fused)
__device__ float g_hnew[(size_t)Bn*TC*HW];
__device__ float g_ta [(size_t)Bn*HID*HW];
__device__ float g_tb [(size_t)Bn*HID*HW];
__device__ float g_gn [128];

__device__ __forceinline__ float sigmoidf_(float x){ return 1.0f/(1.0f+expf(-x)); }

__device__ __forceinline__ void mma_tf32(float* c, unsigned a0, unsigned a1,
                                         unsigned a2, unsigned a3,
                                         unsigned b0, unsigned b1) {
    asm volatile(
        "mma.sync.aligned.m16n8k8.row.col.f32.tf32.tf32.f32 "
        "{%0,%1,%2,%3}, {%4,%5,%6,%7}, {%8,%9}, {%0,%1,%2,%3};"
        : "+f"(c[0]), "+f"(c[1]), "+f"(c[2]), "+f"(c[3])
        : "r"(a0), "r"(a1), "r"(a2), "r"(a3), "r"(b0), "r"(b1));
}

__device__ __forceinline__ void cp16(uint32_t dst, const void* src, int szbytes){
    asm volatile("cp.async.cg.shared.global [%0], [%1], 16, %2;"
                 :: "r"(dst), "l"(src), "r"(szbytes));
}
__device__ __forceinline__ void cp_commit(){ asm volatile("cp.async.commit_group;"); }
__device__ __forceinline__ void cp_wait_all(){ asm volatile("cp.async.wait_all;" ::: "memory"); }

// ---------------------------------------------------------------------------
// K1: build hctx = [feat(64), fL(64), fR_w(64), d, sx, sy, conf, cost(40)]
// ---------------------------------------------------------------------------
__global__ void build_hctx_k(const float* __restrict__ d_, const float* __restrict__ sx,
                             const float* __restrict__ sy, const float* __restrict__ conf,
                             const float* __restrict__ feat, const float* __restrict__ fL,
                             const float* __restrict__ fR)
{
    int idx = blockIdx.x*blockDim.x + threadIdx.x;
    if (idx >= NPIX) return;
    int w = idx & (Wc-1);
    int h = (idx >> 8) & (Hc-1);
    int b = idx >> 15;
    size_t p = (size_t)h*Wc + w;
    size_t pix = (size_t)idx;

    float d0 = d_[pix];

    int i0[Dd], i1[Dd]; float fr[Dd];
#pragma unroll
    for (int o = 0; o < Dd; o++) {
        float xs = (float)w - d0 - (float)(o - HR);
        xs = fminf(fmaxf(xs, 0.0f), (float)(Wc-1));
        float x0f = floorf(xs);
        i0[o] = (int)x0f;
        i1[o] = min(i0[o] + 1, Wc-1);
        fr[o] = xs - x0f;
    }

    size_t hb = (size_t)b * GRU_IN * HW;
    float cost[Dd] = {0.f,0.f,0.f,0.f,0.f};

    for (int c = 0; c < FC; c++) {
        size_t fbase = ((size_t)(b*FC + c)) * HW;
        float fl = fL[fbase + p];
        g_hctx[hb + (size_t)(64 + c)*HW + p] = fl;
        g_hctx[hb + (size_t)c*HW + p]        = feat[fbase + p];
        const float* fRrow = fR + fbase + (size_t)h*Wc;
#pragma unroll
        for (int o = 0; o < Dd; o++) {
            float s = fRrow[i0[o]]*(1.0f-fr[o]) + fRrow[i1[o]]*fr[o];
            cost[o] += fl * s;
            if (o == HR) g_hctx[hb + (size_t)(128 + c)*HW + p] = s;
        }
        if ((c & (CG-1)) == (CG-1)) {
            int g = c >> 3;
#pragma unroll
            for (int o = 0; o < Dd; o++) {
                g_hctx[hb + (size_t)(196 + g*Dd + o)*HW + p] = cost[o] * (1.0f/(float)CG);
                cost[o] = 0.f;
            }
        }
    }
    g_hctx[hb + (size_t)192*HW + p] = d0;
    g_hctx[hb + (size_t)193*HW + p] = sx[pix];
    g_hctx[hb + (size_t)194*HW + p] = sy[pix];
    g_hctx[hb + (size_t)195*HW + p] = conf[pix];
}

// ---------------------------------------------------------------------------
// Tensor-core 3x3 conv (pad=1), implicit GEMM, tf32 mma, cp.async double-buffer.
// CTA tile = full row (256 px) x OC channels. NW warps = 4 (px quad) x NW/4 (oc).
// MODE 0: plain (trunk)   MODE 2: GRU combine (q)   MODE 4: fused z|r
// Input split across two tensors: first CA channels from inA@A0, rest inB@B0.
// For MODE 4 / OC=128: oc<64 uses wgtA/biasA -> out(z); oc>=64 wgtB/biasB ->
// out2(r) with sigmoid*feat.
// ---------------------------------------------------------------------------
template<int IC, int OC, int THREADS, int MODE>
__global__ void __launch_bounds__(THREADS, (THREADS==512)?1:2)
conv3x3_cp_k(const float* __restrict__ inA, int CAtot, int A0, int CA,
             const float* __restrict__ inB, int CBtot, int B0,
             const float* __restrict__ wgtA, const float* __restrict__ wgtB,
             const float* __restrict__ biasA, const float* __restrict__ biasB,
             float* __restrict__ out,
             const float* __restrict__ zbuf, const float* __restrict__ featbuf,
             float* __restrict__ out2)
{
    constexpr int NW   = THREADS/32;
    constexpr int OCW  = OC/(NW/4);
    constexpr int NF   = OCW/8;
    constexpr int NCHK = (IC + 7)/8;
    constexpr int PI   = 264;            // ism row pitch (words)
    constexpr int IST  = 8*3*PI;         // ism words per stage
    constexpr int PW   = 76;             // wsm oc pitch (words)
    constexpr int WST  = OC*PW;          // wsm words per stage

    extern __shared__ unsigned dsm[];
    // layout: [ism stage0][ism stage1][wsm stage0][wsm stage1]
    uint32_t smem_b = (uint32_t)__cvta_generic_to_shared(dsm);

    const int tid  = threadIdx.x;
    const int lane = tid & 31;
    const int warp = tid >> 5;
    const int wm   = warp & 3;
    const int wn   = warp >> 2;
    const int h    = blockIdx.x;
    const int b    = blockIdx.y;
    const int gID  = lane >> 2;
    const int tig  = lane & 3;

    float acc[4][NF][4];
#pragma unroll
    for (int mf = 0; mf < 4; mf++)
#pragma unroll
        for (int f = 0; f < NF; f++)
#pragma unroll
            for (int j = 0; j < 4; j++) acc[mf][f][j] = 0.f;

    // ---- staging helpers (inline) ----
    auto stage = [&](int chunk, int s) {
        // input: 24 row-tasks (icl 0..7, ky 0..2)
        for (int t = warp; t < 24; t += NW) {
            int icl = t / 3;
            int ky  = t - icl*3;
            int ic  = chunk*8 + icl;
            int gy  = h - 1 + ky;
            bool valid = (ic < IC) && (gy >= 0) && (gy < Hc);
            int icc = valid ? ic : 0;
            int gyc = min(max(gy, 0), Hc-1);
            const float* srcrow;
            if (icc < CA) srcrow = inA + (((size_t)b*CAtot + A0 + icc)*Hc + gyc)*Wc;
            else          srcrow = inB + (((size_t)b*CBtot + B0 + (icc-CA))*Hc + gyc)*Wc;
            uint32_t dstw = smem_b + ((uint32_t)(s*IST + t*PI))*4u;
            int sz = valid ? 16 : 0;
            cp16(dstw + (4u + (uint32_t)lane*4u)*4u,      srcrow + lane*4,      sz);
            cp16(dstw + (4u + (uint32_t)(lane+32)*4u)*4u, srcrow + (lane+32)*4, sz);
            if (lane == 0) dsm[s*IST + t*PI + 3]   = 0u;   // left pad (x=-1)
            if (lane == 1) dsm[s*IST + t*PI + 260] = 0u;   // right pad (x=256)
        }
        // weights: per oc, 72 contiguous floats (8 ic x 9 taps) = 18 float4
        int validf = min(IC - chunk*8, 8)*9*4;   // valid bytes this chunk
        for (int i = tid; i < OC*18; i += THREADS) {
            int oc = i / 18;
            int j  = i - oc*18;
            int rem = validf - j*16;
            int sz  = rem >= 16 ? 16 : 0;
            const float* src;
            if (OC == 128 && oc >= 64)
                src = wgtB + (size_t)(oc-64)*IC*9 + (size_t)chunk*72 + j*4;
            else
                src = wgtA + (size_t)oc*IC*9 + (size_t)chunk*72 + j*4;
            if (sz == 0) src = wgtA;  // safe address for zfill
            uint32_t dst = smem_b + ((uint32_t)(2*IST + s*WST + oc*PW + j*4))*4u;
            cp16(dst, src, sz);
        }
    };

    stage(0, 0);
    cp_commit();

    for (int c = 0; c < NCHK; c++) {
        cp_wait_all();
        __syncthreads();
        if (c + 1 < NCHK) { stage(c+1, (c+1)&1); cp_commit(); }

        const unsigned* isb = dsm + (c&1)*IST;
        const unsigned* wsb = dsm + 2*IST + (c&1)*WST;

#pragma unroll
        for (int tap = 0; tap < 9; tap++) {
            const int ky = tap/3, kx = tap - (tap/3)*3;
            unsigned b0[NF], b1[NF];
#pragma unroll
            for (int f = 0; f < NF; f++) {
                int oc = wn*OCW + f*8 + gID;
                b0[f] = wsb[oc*PW + tig*9 + tap];
                b1[f] = wsb[oc*PW + (tig+4)*9 + tap];
            }
            const unsigned* ib = isb + ky*PI + kx + 3;
#pragma unroll
            for (int mf = 0; mf < 4; mf++) {
                int p = wm*64 + mf*16 + gID;
                unsigned a0 = ib[ tig   *3*PI + p];
                unsigned a1 = ib[ tig   *3*PI + p + 8];
                unsigned a2 = ib[(tig+4)*3*PI + p];
                unsigned a3 = ib[(tig+4)*3*PI + p + 8];
#pragma unroll
                for (int f = 0; f < NF; f++)
                    mma_tf32(acc[mf][f], a0, a1, a2, a3, b0[f], b1[f]);
            }
        }
    }

    // ---- epilogue ----
#pragma unroll
    for (int mf = 0; mf < 4; mf++) {
#pragma unroll
        for (int f = 0; f < NF; f++) {
            int px0 = wm*64 + mf*16 + gID;
            int oc0 = wn*OCW + f*8 + 2*tig;
#pragma unroll
            for (int e = 0; e < 4; e++) {
                int px = px0 + (e >> 1)*8;
                int oc = oc0 + (e & 1);
                float val = acc[mf][f][e];
                if (MODE == 4) {
                    if (oc < 64) {
                        size_t o = (((size_t)b*64 + oc)*Hc + h)*Wc + px;
                        out[o] = sigmoidf_(val + biasA[oc]);
                    } else {
                        int oc2 = oc - 64;
                        size_t o = (((size_t)b*64 + oc2)*Hc + h)*Wc + px;
                        out2[o] = sigmoidf_(val + biasB[oc2]) * featbuf[o];
                    }
                } else {
                    size_t o = (((size_t)b*OC + oc)*Hc + h)*Wc + px;
                    if (MODE == 0) {
                        out[o] = val + (biasA ? biasA[oc] : 0.f);
                    } else { // MODE 2: GRU combine
                        float q = tanhf(val + biasA[oc]);
                        float z = zbuf[o];
                        float fv = featbuf[o];
                        float hn = (1.0f - z)*fv + z*q;
                        out[o]  = hn;
                        out2[o] = hn;
                    }
                }
            }
        }
    }
}

// ---------------------------------------------------------------------------
// GroupNorm stats: 32 blocks = (b,group)
// ---------------------------------------------------------------------------
__global__ void gn_stats_k(const float* __restrict__ x, int set)
{
    __shared__ float ss[256], ss2[256];
    int bg = blockIdx.x;
    int b  = bg >> 3, g = bg & 7;
    size_t base = ((size_t)b*HID + g*(HID/Gg)) * HW;
    const int N = (HID/Gg) * HW;
    float s = 0.f, s2 = 0.f;
    for (int i = threadIdx.x; i < N; i += 256) {
        float v = x[base + i];
        s += v; s2 += v*v;
    }
    ss[threadIdx.x] = s; ss2[threadIdx.x] = s2;
    __syncthreads();
    for (int off = 128; off > 0; off >>= 1) {
        if (threadIdx.x < off) {
            ss[threadIdx.x]  += ss[threadIdx.x + off];
            ss2[threadIdx.x] += ss2[threadIdx.x + off];
        }
        __syncthreads();
    }
    if (threadIdx.x == 0) {
        float mean = ss[0] / (float)N;
        float var  = ss2[0] / (float)N - mean*mean;
        g_gn[set*64 + bg*2]     = mean;
        g_gn[set*64 + bg*2 + 1] = rsqrtf(var + 1e-5f);
    }
}

// ---------------------------------------------------------------------------
// GroupNorm apply + SiLU
// ---------------------------------------------------------------------------
__global__ void gn_apply_k(const float* __restrict__ x, float* __restrict__ y,
                           const float* __restrict__ scale, const float* __restrict__ bias,
                           int set)
{
    int i = blockIdx.x*blockDim.x + threadIdx.x;
    const int n = Bn*HID*HW;
    if (i >= n) return;
    int c = (i / HW) % HID;
    int b = i / (HID*HW);
    int grp = c / (HID/Gg);
    float mean = g_gn[set*64 + (b*8+grp)*2];
    float rstd = g_gn[set*64 + (b*8+grp)*2 + 1];
    float v = (x[i] - mean)*rstd*scale[c] + bias[c];
    y[i] = v * sigmoidf_(v);
}

// ---------------------------------------------------------------------------
// Heads: four 1x1 convs (48->1) + activations
// ---------------------------------------------------------------------------
__global__ void heads_k(const float* __restrict__ t,
                        const float* __restrict__ d_, const float* __restrict__ sx,
                        const float* __restrict__ sy, const float* __restrict__ conf,
                        const float* __restrict__ wd,  const float* __restrict__ bd,
                        const float* __restrict__ wsx, const float* __restrict__ bsx,
                        const float* __restrict__ wsy, const float* __restrict__ bsy,
                        const float* __restrict__ wcf, const float* __restrict__ bcf,
                        float* __restrict__ out)
{
    __shared__ float wsm[4][HID];
    int tid = threadIdx.x;
    if (tid < HID)              wsm[0][tid]        = wd [tid];
    else if (tid < 2*HID)       wsm[1][tid-HID]    = wsx[tid-HID];
    else if (tid < 3*HID)       wsm[2][tid-2*HID]  = wsy[tid-2*HID];
    else if (tid < 4*HID)       wsm[3][tid-3*HID]  = wcf[tid-3*HID];
    __syncthreads();

    int idx = blockIdx.x*blockDim.x + tid;
    if (idx >= NPIX) return;
    int b = idx >> 15;
    size_t p = (size_t)(idx & (HW-1));
    size_t pix = (size_t)idx;

    float a0=0.f, a1=0.f, a2=0.f, a3=0.f;
    size_t base = (size_t)b*HID*HW + p;
    for (int c = 0; c < HID; c++) {
        float v = t[base + (size_t)c*HW];
        a0 = fmaf(v, wsm[0][c], a0);
        a1 = fmaf(v, wsm[1][c], a1);
        a2 = fmaf(v, wsm[2][c], a2);
        a3 = fmaf(v, wsm[3][c], a3);
    }
    float ad = a0 + bd[0] + d_[pix];
    out[O_D + pix]  = (ad > 20.0f) ? ad : log1pf(expf(ad));
    out[O_SX + pix] = sx[pix] + (a1 + bsx[0]) * 0.1f;
    out[O_SY + pix] = sy[pix] + (a2 + bsy[0]) * 0.1f;
    out[O_CONF + pix] = sigmoidf_(a3 + bcf[0] + 2.0f*conf[pix] - 1.0f);
}

// ---------------------------------------------------------------------------
extern "C" void kernel_launch(void* const* d_in, const int* in_sizes, int n_in,
                              void* d_out, int out_size)
{
    const float* d_   = (const float*)d_in[0];
    const float* sx   = (const float*)d_in[1];
    const float* sy   = (const float*)d_in[2];
    const float* conf = (const float*)d_in[3];
    const float* feat = (const float*)d_in[4];
    const float* fL   = (const float*)d_in[5];
    const float* fR   = (const float*)d_in[6];
    const float* wz   = (const float*)d_in[7];
    const float* bz   = (const float*)d_in[8];
    const float* wr   = (const float*)d_in[9];
    const float* br   = (const float*)d_in[10];
    const float* wq   = (const float*)d_in[11];
    const float* bq   = (const float*)d_in[12];
    const float* w1   = (const float*)d_in[13];
    const float* g1s  = (const float*)d_in[14];
    const float* g1b  = (const float*)d_in[15];
    const float* w2   = (const float*)d_in[16];
    const float* g2s  = (const float*)d_in[17];
    const float* g2b  = (const float*)d_in[18];
    const float* whd  = (const float*)d_in[19];
    const float* bhd  = (const float*)d_in[20];
    const float* whx  = (const float*)d_in[21];
    const float* bhx  = (const float*)d_in[22];
    const float* why  = (const float*)d_in[23];
    const float* bhy  = (const float*)d_in[24];
    const float* whc  = (const float*)d_in[25];
    const float* bhc  = (const float*)d_in[26];
    float* out = (float*)d_out;

    float *hctx, *z, *r, *hnew, *ta, *tb;
    cudaGetSymbolAddress((void**)&hctx, g_hctx);
    cudaGetSymbolAddress((void**)&z,    g_z);
    cudaGetSymbolAddress((void**)&r,    g_r);
    cudaGetSymbolAddress((void**)&hnew, g_hnew);
    cudaGetSymbolAddress((void**)&ta,   g_ta);
    cudaGetSymbolAddress((void**)&tb,   g_tb);

    // smem sizes (2 stages of ism + wsm)
    const int IST = 8*3*264;
    const int SM_ZR = 2*(IST + 128*76)*4;   // 128512
    const int SM_Q  = 2*(IST + 64*76)*4;    //  89600
    const int SM_T  = 2*(IST + 48*76)*4;    //  79872

    cudaFuncSetAttribute(conv3x3_cp_k<GRU_IN,128,512,4>,
                         cudaFuncAttributeMaxDynamicSharedMemorySize, SM_ZR);
    cudaFuncSetAttribute(conv3x3_cp_k<GRU_IN,64,256,2>,
                         cudaFuncAttributeMaxDynamicSharedMemorySize, SM_Q);
    cudaFuncSetAttribute(conv3x3_cp_k<TC,HID,256,0>,
                         cudaFuncAttributeMaxDynamicSharedMemorySize, SM_T);
    cudaFuncSetAttribute(conv3x3_cp_k<HID,HID,256,0>,
                         cudaFuncAttributeMaxDynamicSharedMemorySize, SM_T);

    dim3 cgrid(Hc, Bn);

    build_hctx_k<<<NPIX/256, 256>>>(d_, sx, sy, conf, feat, fL, fR);

    // fused z|r conv: z = sigmoid(conv_z(hctx)); r*feat = sigmoid(conv_r(hctx))*feat
    conv3x3_cp_k<GRU_IN,128,512,4><<<cgrid, 512, SM_ZR>>>(
        hctx, GRU_IN, 0, GRU_IN, nullptr, 0, 0,
        wz, wr, bz, br, z, nullptr, feat, r);

    // q conv + GRU combine -> hnew (and output h slot)
    conv3x3_cp_k<GRU_IN,64,256,2><<<cgrid, 256, SM_Q>>>(
        r, TC, 0, TC, hctx, GRU_IN, 64,
        wq, nullptr, bq, nullptr, hnew, z, feat, out + O_H);

    conv3x3_cp_k<TC,HID,256,0><<<cgrid, 256, SM_T>>>(
        hnew, TC, 0, TC, nullptr, 0, 0,
        w1, nullptr, nullptr, nullptr, ta, nullptr, nullptr, nullptr);
    gn_stats_k<<<32, 256>>>(ta, 0);
    gn_apply_k<<<(Bn*HID*HW)/256, 256>>>(ta, tb, g1s, g1b, 0);

    conv3x3_cp_k<HID,HID,256,0><<<cgrid, 256, SM_T>>>(
        tb, HID, 0, HID, nullptr, 0, 0,
        w2, nullptr, nullptr, nullptr, ta, nullptr, nullptr, nullptr);
    gn_stats_k<<<32, 256>>>(ta, 1);
    gn_apply_k<<<(Bn*HID*HW)/256, 256>>>(ta, tb, g2s, g2b, 1);

    heads_k<<<NPIX/256, 256>>>(tb, d_, sx, sy, conf,
                               whd, bhd, whx, bhx, why, bhy, whc, bhc, out);
}

// round 8
// speedup vs baseline: 5.4337x; 1.0630x over previous
#include <cuda_runtime.h>
#include <cuda_bf16.h>
#include <math.h>
#include <stdint.h>

// Problem constants
#define Bn 4
#define FC 64
#define TC 64
#define HID 48
#define HR 2
#define Gg 8
#define Hc 128
#define Wc 256
#define Dd 5
#define CG 8
#define GRU_IN 236
#define HCTX 108
#define HW (Hc*Wc)            // 32768
#define NPIX (Bn*HW)          // 131072

// Output layout (flattened tuple in return order)
#define O_D    0
#define O_SX   (NPIX)
#define O_SY   (2*NPIX)
#define O_H    (3*NPIX)
#define O_CONF (3*NPIX + Bn*TC*HW)

// Scratch (device globals; no allocation allowed)
__device__ float g_hctx[(size_t)Bn*HCTX*HW];     // [fR_w(64), d,sx,sy,conf(4), cost(40)]
__device__ float g_z  [(size_t)Bn*TC*HW];
__device__ float g_r  [(size_t)Bn*TC*HW];        // holds r*feat (fused)
__device__ float g_hnew[(size_t)Bn*TC*HW];
__device__ float g_ta [(size_t)Bn*HID*HW];
__device__ float g_tb [(size_t)Bn*HID*HW];
__device__ float g_gn [128];

__device__ __forceinline__ float sigmoidf_(float x){ return 1.0f/(1.0f+expf(-x)); }

__device__ __forceinline__ void mma_tf32(float* c, unsigned a0, unsigned a1,
                                         unsigned a2, unsigned a3,
                                         unsigned b0, unsigned b1) {
    asm volatile(
        "mma.sync.aligned.m16n8k8.row.col.f32.tf32.tf32.f32 "
        "{%0,%1,%2,%3}, {%4,%5,%6,%7}, {%8,%9}, {%0,%1,%2,%3};"
        : "+f"(c[0]), "+f"(c[1]), "+f"(c[2]), "+f"(c[3])
        : "r"(a0), "r"(a1), "r"(a2), "r"(a3), "r"(b0), "r"(b1));
}

__device__ __forceinline__ void cp16(uint32_t dst, const void* src, int szbytes){
    asm volatile("cp.async.cg.shared.global [%0], [%1], 16, %2;"
                 :: "r"(dst), "l"(src), "r"(szbytes));
}
__device__ __forceinline__ void cp_commit(){ asm volatile("cp.async.commit_group;"); }
__device__ __forceinline__ void cp_wait_all(){ asm volatile("cp.async.wait_all;" ::: "memory"); }

// ---------------------------------------------------------------------------
// K1: build hctx108 = [fR_w(64), d, sx, sy, conf, cost(40)]
// 2 threads per pixel: half 0 handles channels 0-31, half 1 handles 32-63.
// ---------------------------------------------------------------------------
__global__ void build_hctx_k(const float* __restrict__ d_, const float* __restrict__ sx,
                             const float* __restrict__ sy, const float* __restrict__ conf,
                             const float* __restrict__ fL, const float* __restrict__ fR)
{
    int idx = blockIdx.x*blockDim.x + threadIdx.x;
    if (idx >= 2*NPIX) return;
    int half = idx & 1;
    int pixi = idx >> 1;
    int w = pixi & (Wc-1);
    int h = (pixi >> 8) & (Hc-1);
    int b = pixi >> 15;
    size_t p = (size_t)h*Wc + w;
    size_t pix = (size_t)pixi;

    float d0 = d_[pix];

    int i0[Dd], i1[Dd]; float fr[Dd];
#pragma unroll
    for (int o = 0; o < Dd; o++) {
        float xs = (float)w - d0 - (float)(o - HR);
        xs = fminf(fmaxf(xs, 0.0f), (float)(Wc-1));
        float x0f = floorf(xs);
        i0[o] = (int)x0f;
        i1[o] = min(i0[o] + 1, Wc-1);
        fr[o] = xs - x0f;
    }

    size_t hb = (size_t)b * HCTX * HW;
    float cost[Dd] = {0.f,0.f,0.f,0.f,0.f};

    int c0 = half*32;
    for (int c = c0; c < c0+32; c++) {
        size_t fbase = ((size_t)(b*FC + c)) * HW;
        float fl = fL[fbase + p];
        const float* fRrow = fR + fbase + (size_t)h*Wc;
#pragma unroll
        for (int o = 0; o < Dd; o++) {
            float s = fRrow[i0[o]]*(1.0f-fr[o]) + fRrow[i1[o]]*fr[o];
            cost[o] += fl * s;
            if (o == HR) g_hctx[hb + (size_t)c*HW + p] = s;   // fR_w
        }
        if ((c & (CG-1)) == (CG-1)) {
            int g = c >> 3;
#pragma unroll
            for (int o = 0; o < Dd; o++) {
                g_hctx[hb + (size_t)(68 + g*Dd + o)*HW + p] = cost[o] * (1.0f/(float)CG);
                cost[o] = 0.f;
            }
        }
    }
    if (half == 0) {
        g_hctx[hb + (size_t)64*HW + p] = d0;
        g_hctx[hb + (size_t)65*HW + p] = sx[pix];
        g_hctx[hb + (size_t)66*HW + p] = sy[pix];
        g_hctx[hb + (size_t)67*HW + p] = conf[pix];
    }
}

// ---------------------------------------------------------------------------
// Tensor-core 3x3 conv (pad=1), implicit GEMM, tf32 mma, cp.async double-buffer.
// Input channels resolved over up to 3 source tensors:
//   ic <  64 -> p0[b][ic]          (C0tot channels per batch)
//   ic < 128 -> p1[b][ic-64]
//   else     -> p2[b][ic-128]
// MODE 0: plain   MODE 2: GRU combine (q)   MODE 4: fused z|r (OC=128)
// ---------------------------------------------------------------------------
template<int IC, int OC, int THREADS, int MODE>
__global__ void __launch_bounds__(THREADS, (THREADS==512)?1:2)
conv3x3_cp_k(const float* __restrict__ p0, int C0tot,
             const float* __restrict__ p1, int C1tot,
             const float* __restrict__ p2, int C2tot,
             const float* __restrict__ wgtA, const float* __restrict__ wgtB,
             const float* __restrict__ biasA, const float* __restrict__ biasB,
             float* __restrict__ out,
             const float* __restrict__ zbuf, const float* __restrict__ featbuf,
             float* __restrict__ out2)
{
    constexpr int NW   = THREADS/32;
    constexpr int OCW  = OC/(NW/4);
    constexpr int NF   = OCW/8;
    constexpr int NCHK = (IC + 7)/8;
    constexpr int PI   = 264;            // ism row pitch (words)
    constexpr int IST  = 8*3*PI;         // ism words per stage
    constexpr int PW   = 76;             // wsm oc pitch (words)
    constexpr int WST  = OC*PW;          // wsm words per stage

    extern __shared__ unsigned dsm[];
    uint32_t smem_b = (uint32_t)__cvta_generic_to_shared(dsm);

    const int tid  = threadIdx.x;
    const int lane = tid & 31;
    const int warp = tid >> 5;
    const int wm   = warp & 3;
    const int wn   = warp >> 2;
    const int h    = blockIdx.x;
    const int b    = blockIdx.y;
    const int gID  = lane >> 2;
    const int tig  = lane & 3;

    float acc[4][NF][4];
#pragma unroll
    for (int mf = 0; mf < 4; mf++)
#pragma unroll
        for (int f = 0; f < NF; f++)
#pragma unroll
            for (int j = 0; j < 4; j++) acc[mf][f][j] = 0.f;

    auto stage = [&](int chunk, int s) {
        // input: 24 row-tasks (icl 0..7, ky 0..2)
        for (int t = warp; t < 24; t += NW) {
            int icl = t / 3;
            int ky  = t - icl*3;
            int ic  = chunk*8 + icl;
            int gy  = h - 1 + ky;
            bool valid = (ic < IC) && (gy >= 0) && (gy < Hc);
            int icc = valid ? ic : 0;
            int gyc = min(max(gy, 0), Hc-1);
            const float* srcrow;
            if (icc < 64)       srcrow = p0 + (((size_t)b*C0tot + icc)*Hc + gyc)*Wc;
            else if (icc < 128) srcrow = p1 + (((size_t)b*C1tot + (icc-64))*Hc + gyc)*Wc;
            else                srcrow = p2 + (((size_t)b*C2tot + (icc-128))*Hc + gyc)*Wc;
            uint32_t dstw = smem_b + ((uint32_t)(s*IST + t*PI))*4u;
            int sz = valid ? 16 : 0;
            cp16(dstw + (4u + (uint32_t)lane*4u)*4u,      srcrow + lane*4,      sz);
            cp16(dstw + (4u + (uint32_t)(lane+32)*4u)*4u, srcrow + (lane+32)*4, sz);
            if (lane == 0) dsm[s*IST + t*PI + 3]   = 0u;   // left pad
            if (lane == 1) dsm[s*IST + t*PI + 260] = 0u;   // right pad
        }
        // weights: per oc, 72 contiguous floats (8 ic x 9 taps) = 18 float4
        int validf = min(IC - chunk*8, 8)*9*4;
        for (int i = tid; i < OC*18; i += THREADS) {
            int oc = i / 18;
            int j  = i - oc*18;
            int rem = validf - j*16;
            int sz  = rem >= 16 ? 16 : 0;
            const float* src;
            if (OC == 128 && oc >= 64)
                src = wgtB + (size_t)(oc-64)*IC*9 + (size_t)chunk*72 + j*4;
            else
                src = wgtA + (size_t)oc*IC*9 + (size_t)chunk*72 + j*4;
            if (sz == 0) src = wgtA;
            uint32_t dst = smem_b + ((uint32_t)(2*IST + s*WST + oc*PW + j*4))*4u;
            cp16(dst, src, sz);
        }
    };

    stage(0, 0);
    cp_commit();

    for (int c = 0; c < NCHK; c++) {
        cp_wait_all();
        __syncthreads();
        if (c + 1 < NCHK) { stage(c+1, (c+1)&1); cp_commit(); }

        const unsigned* isb = dsm + (c&1)*IST;
        const unsigned* wsb = dsm + 2*IST + (c&1)*WST;

#pragma unroll
        for (int tap = 0; tap < 9; tap++) {
            const int ky = tap/3, kx = tap - (tap/3)*3;
            unsigned b0[NF], b1[NF];
#pragma unroll
            for (int f = 0; f < NF; f++) {
                int oc = wn*OCW + f*8 + gID;
                b0[f] = wsb[oc*PW + tig*9 + tap];
                b1[f] = wsb[oc*PW + (tig+4)*9 + tap];
            }
            const unsigned* ib = isb + ky*PI + kx + 3;
#pragma unroll
            for (int mf = 0; mf < 4; mf++) {
                int p = wm*64 + mf*16 + gID;
                unsigned a0 = ib[ tig   *3*PI + p];
                unsigned a1 = ib[ tig   *3*PI + p + 8];
                unsigned a2 = ib[(tig+4)*3*PI + p];
                unsigned a3 = ib[(tig+4)*3*PI + p + 8];
#pragma unroll
                for (int f = 0; f < NF; f++)
                    mma_tf32(acc[mf][f], a0, a1, a2, a3, b0[f], b1[f]);
            }
        }
    }

    // ---- epilogue ----
#pragma unroll
    for (int mf = 0; mf < 4; mf++) {
#pragma unroll
        for (int f = 0; f < NF; f++) {
            int px0 = wm*64 + mf*16 + gID;
            int oc0 = wn*OCW + f*8 + 2*tig;
#pragma unroll
            for (int e = 0; e < 4; e++) {
                int px = px0 + (e >> 1)*8;
                int oc = oc0 + (e & 1);
                float val = acc[mf][f][e];
                if (MODE == 4) {
                    if (oc < 64) {
                        size_t o = (((size_t)b*64 + oc)*Hc + h)*Wc + px;
                        out[o] = sigmoidf_(val + biasA[oc]);
                    } else {
                        int oc2 = oc - 64;
                        size_t o = (((size_t)b*64 + oc2)*Hc + h)*Wc + px;
                        out2[o] = sigmoidf_(val + biasB[oc2]) * featbuf[o];
                    }
                } else {
                    size_t o = (((size_t)b*OC + oc)*Hc + h)*Wc + px;
                    if (MODE == 0) {
                        out[o] = val + (biasA ? biasA[oc] : 0.f);
                    } else { // MODE 2: GRU combine
                        float q = tanhf(val + biasA[oc]);
                        float z = zbuf[o];
                        float fv = featbuf[o];
                        float hn = (1.0f - z)*fv + z*q;
                        out[o]  = hn;
                        out2[o] = hn;
                    }
                }
            }
        }
    }
}

// ---------------------------------------------------------------------------
// GroupNorm stats: 32 blocks = (b,group), 512 threads, float4
// ---------------------------------------------------------------------------
__global__ void gn_stats_k(const float* __restrict__ x, int set)
{
    __shared__ float ss[512], ss2[512];
    int bg = blockIdx.x;
    int b  = bg >> 3, g = bg & 7;
    size_t base = ((size_t)b*HID + g*(HID/Gg)) * HW;
    const int N4 = ((HID/Gg) * HW) / 4;
    const float4* x4 = (const float4*)(x + base);
    float s = 0.f, s2 = 0.f;
    for (int i = threadIdx.x; i < N4; i += 512) {
        float4 v = x4[i];
        s  += v.x + v.y + v.z + v.w;
        s2 += v.x*v.x + v.y*v.y + v.z*v.z + v.w*v.w;
    }
    ss[threadIdx.x] = s; ss2[threadIdx.x] = s2;
    __syncthreads();
    for (int off = 256; off > 0; off >>= 1) {
        if (threadIdx.x < off) {
            ss[threadIdx.x]  += ss[threadIdx.x + off];
            ss2[threadIdx.x] += ss2[threadIdx.x + off];
        }
        __syncthreads();
    }
    if (threadIdx.x == 0) {
        const float Nf = (float)((HID/Gg)*HW);
        float mean = ss[0] / Nf;
        float var  = ss2[0] / Nf - mean*mean;
        g_gn[set*64 + bg*2]     = mean;
        g_gn[set*64 + bg*2 + 1] = rsqrtf(var + 1e-5f);
    }
}

// ---------------------------------------------------------------------------
// GroupNorm apply + SiLU (float4)
// ---------------------------------------------------------------------------
__global__ void gn_apply_k(const float* __restrict__ x, float* __restrict__ y,
                           const float* __restrict__ scale, const float* __restrict__ bias,
                           int set)
{
    int i4 = blockIdx.x*blockDim.x + threadIdx.x;
    const int n4 = (Bn*HID*HW)/4;
    if (i4 >= n4) return;
    int i = i4*4;
    int c = (i / HW) % HID;
    int b = i / (HID*HW);
    int grp = c / (HID/Gg);
    float mean = g_gn[set*64 + (b*8+grp)*2];
    float rstd = g_gn[set*64 + (b*8+grp)*2 + 1];
    float sc = scale[c]*rstd, bi = bias[c] - mean*rstd*scale[c];
    float4 v = ((const float4*)x)[i4];
    float4 o;
    float t;
    t = v.x*sc + bi; o.x = t * sigmoidf_(t);
    t = v.y*sc + bi; o.y = t * sigmoidf_(t);
    t = v.z*sc + bi; o.z = t * sigmoidf_(t);
    t = v.w*sc + bi; o.w = t * sigmoidf_(t);
    ((float4*)y)[i4] = o;
}

// ---------------------------------------------------------------------------
// Heads: fused GN2-apply + SiLU + four 1x1 convs (48->1) + activations.
// Reads raw trunk2 conv output (ta) + gn set-1 stats.
// ---------------------------------------------------------------------------
__global__ void heads_k(const float* __restrict__ t,
                        const float* __restrict__ gnsc, const float* __restrict__ gnbi,
                        const float* __restrict__ d_, const float* __restrict__ sx,
                        const float* __restrict__ sy, const float* __restrict__ conf,
                        const float* __restrict__ wd,  const float* __restrict__ bd,
                        const float* __restrict__ wsx, const float* __restrict__ bsx,
                        const float* __restrict__ wsy, const float* __restrict__ bsy,
                        const float* __restrict__ wcf, const float* __restrict__ bcf,
                        float* __restrict__ out)
{
    __shared__ float wsm[4][HID];
    __shared__ float csc[HID], cbi[HID];   // folded per-channel scale/bias wait per-batch mean...
    int tid = threadIdx.x;
    if (tid < HID)              wsm[0][tid]        = wd [tid];
    else if (tid < 2*HID)       wsm[1][tid-HID]    = wsx[tid-HID];
    else if (tid < 3*HID)       wsm[2][tid-2*HID]  = wsy[tid-2*HID];
    else if (tid < 4*HID)       wsm[3][tid-3*HID]  = wcf[tid-3*HID];
    if (tid < HID) { csc[tid] = gnsc[tid]; cbi[tid] = gnbi[tid]; }
    __syncthreads();

    int idx = blockIdx.x*blockDim.x + tid;
    if (idx >= NPIX) return;
    int b = idx >> 15;
    size_t p = (size_t)(idx & (HW-1));
    size_t pix = (size_t)idx;

    // per-batch group stats (set 1)
    float gmean[8], grstd[8];
#pragma unroll
    for (int g = 0; g < 8; g++) {
        gmean[g] = g_gn[64 + (b*8+g)*2];
        grstd[g] = g_gn[64 + (b*8+g)*2 + 1];
    }

    float a0=0.f, a1=0.f, a2=0.f, a3=0.f;
    size_t base = (size_t)b*HID*HW + p;
#pragma unroll
    for (int c = 0; c < HID; c++) {
        int g = c / (HID/Gg);
        float v = (t[base + (size_t)c*HW] - gmean[g])*grstd[g]*csc[c] + cbi[c];
        v = v * sigmoidf_(v);
        a0 = fmaf(v, wsm[0][c], a0);
        a1 = fmaf(v, wsm[1][c], a1);
        a2 = fmaf(v, wsm[2][c], a2);
        a3 = fmaf(v, wsm[3][c], a3);
    }
    float ad = a0 + bd[0] + d_[pix];
    out[O_D + pix]  = (ad > 20.0f) ? ad : log1pf(expf(ad));
    out[O_SX + pix] = sx[pix] + (a1 + bsx[0]) * 0.1f;
    out[O_SY + pix] = sy[pix] + (a2 + bsy[0]) * 0.1f;
    out[O_CONF + pix] = sigmoidf_(a3 + bcf[0] + 2.0f*conf[pix] - 1.0f);
}

// ---------------------------------------------------------------------------
extern "C" void kernel_launch(void* const* d_in, const int* in_sizes, int n_in,
                              void* d_out, int out_size)
{
    const float* d_   = (const float*)d_in[0];
    const float* sx   = (const float*)d_in[1];
    const float* sy   = (const float*)d_in[2];
    const float* conf = (const float*)d_in[3];
    const float* feat = (const float*)d_in[4];
    const float* fL   = (const float*)d_in[5];
    const float* fR   = (const float*)d_in[6];
    const float* wz   = (const float*)d_in[7];
    const float* bz   = (const float*)d_in[8];
    const float* wr   = (const float*)d_in[9];
    const float* br   = (const float*)d_in[10];
    const float* wq   = (const float*)d_in[11];
    const float* bq   = (const float*)d_in[12];
    const float* w1   = (const float*)d_in[13];
    const float* g1s  = (const float*)d_in[14];
    const float* g1b  = (const float*)d_in[15];
    const float* w2   = (const float*)d_in[16];
    const float* g2s  = (const float*)d_in[17];
    const float* g2b  = (const float*)d_in[18];
    const float* whd  = (const float*)d_in[19];
    const float* bhd  = (const float*)d_in[20];
    const float* whx  = (const float*)d_in[21];
    const float* bhx  = (const float*)d_in[22];
    const float* why  = (const float*)d_in[23];
    const float* bhy  = (const float*)d_in[24];
    const float* whc  = (const float*)d_in[25];
    const float* bhc  = (const float*)d_in[26];
    float* out = (float*)d_out;

    float *hctx, *z, *r, *hnew, *ta, *tb;
    cudaGetSymbolAddress((void**)&hctx, g_hctx);
    cudaGetSymbolAddress((void**)&z,    g_z);
    cudaGetSymbolAddress((void**)&r,    g_r);
    cudaGetSymbolAddress((void**)&hnew, g_hnew);
    cudaGetSymbolAddress((void**)&ta,   g_ta);
    cudaGetSymbolAddress((void**)&tb,   g_tb);

    const int IST = 8*3*264;
    const int SM_ZR = 2*(IST + 128*76)*4;   // 128512
    const int SM_Q  = 2*(IST + 64*76)*4;    //  89600
    const int SM_T  = 2*(IST + 48*76)*4;    //  79872

    cudaFuncSetAttribute(conv3x3_cp_k<GRU_IN,128,512,4>,
                         cudaFuncAttributeMaxDynamicSharedMemorySize, SM_ZR);
    cudaFuncSetAttribute(conv3x3_cp_k<GRU_IN,64,256,2>,
                         cudaFuncAttributeMaxDynamicSharedMemorySize, SM_Q);
    cudaFuncSetAttribute(conv3x3_cp_k<TC,HID,256,0>,
                         cudaFuncAttributeMaxDynamicSharedMemorySize, SM_T);
    cudaFuncSetAttribute(conv3x3_cp_k<HID,HID,256,0>,
                         cudaFuncAttributeMaxDynamicSharedMemorySize, SM_T);

    dim3 cgrid(Hc, Bn);

    build_hctx_k<<<(2*NPIX)/256, 256>>>(d_, sx, sy, conf, fL, fR);

    // fused z|r conv: z = sigmoid(conv_z); r*feat = sigmoid(conv_r)*feat
    // sources: feat(0-63) | fL(64-127) | hctx108(128-235)
    conv3x3_cp_k<GRU_IN,128,512,4><<<cgrid, 512, SM_ZR>>>(
        feat, 64, fL, 64, hctx, HCTX,
        wz, wr, bz, br, z, nullptr, feat, r);

    // q conv + GRU combine -> hnew (and output h slot)
    // sources: r*feat(0-63) | fL(64-127) | hctx108(128-235)
    conv3x3_cp_k<GRU_IN,64,256,2><<<cgrid, 256, SM_Q>>>(
        r, 64, fL, 64, hctx, HCTX,
        wq, nullptr, bq, nullptr, hnew, z, feat, out + O_H);

    conv3x3_cp_k<TC,HID,256,0><<<cgrid, 256, SM_T>>>(
        hnew, TC, hnew, TC, hnew, TC,
        w1, nullptr, nullptr, nullptr, ta, nullptr, nullptr, nullptr);
    gn_stats_k<<<32, 512>>>(ta, 0);
    gn_apply_k<<<(Bn*HID*HW)/4/256, 256>>>(ta, tb, g1s, g1b, 0);

    conv3x3_cp_k<HID,HID,256,0><<<cgrid, 256, SM_T>>>(
        tb, HID, tb, HID, tb, HID,
        w2, nullptr, nullptr, nullptr, ta, nullptr, nullptr, nullptr);
    gn_stats_k<<<32, 512>>>(ta, 1);

    // heads with fused GN2 apply + SiLU
    heads_k<<<NPIX/256, 256>>>(ta, g2s, g2b, d_, sx, sy, conf,
                               whd, bhd, whx, bhx, why, bhy, whc, bhc, out);
}

// round 9
// speedup vs baseline: 5.5566x; 1.0226x over previous
#include <cuda_runtime.h>
#include <cuda_bf16.h>
#include <math.h>
#include <stdint.h>

// Problem constants
#define Bn 4
#define FC 64
#define TC 64
#define HID 48
#define HR 2
#define Gg 8
#define Hc 128
#define Wc 256
#define Dd 5
#define CG 8
#define GRU_IN 236
#define HCTX 108
#define HW (Hc*Wc)            // 32768
#define NPIX (Bn*HW)          // 131072

// Output layout (flattened tuple in return order)
#define O_D    0
#define O_SX   (NPIX)
#define O_SY   (2*NPIX)
#define O_H    (3*NPIX)
#define O_CONF (3*NPIX + Bn*TC*HW)

// Scratch (device globals; no allocation allowed)
__device__ float g_hctx[(size_t)Bn*HCTX*HW];     // [fR_w(64), d,sx,sy,conf(4), cost(40)]
__device__ float g_z  [(size_t)Bn*TC*HW];
__device__ float g_r  [(size_t)Bn*TC*HW];        // holds r*feat (fused)
__device__ float g_hnew[(size_t)Bn*TC*HW];
__device__ float g_ta [(size_t)Bn*HID*HW];
__device__ float g_tb [(size_t)Bn*HID*HW];
__device__ float g_gn [128];

// Fragment-permuted tf32 weights: [chunk][tap][ocq][lane] -> float2 {b0,b1}
__device__ float2 g_wzr[30*9*16*32];   // z|r fused, OC=128
__device__ float2 g_wq [30*9* 8*32];   // q, OC=64
__device__ float2 g_wt1[ 8*9* 6*32];   // trunk1, IC=64, OC=48
__device__ float2 g_wt2[ 6*9* 6*32];   // trunk2, IC=48, OC=48

__device__ __forceinline__ float sigmoidf_(float x){ return 1.0f/(1.0f+expf(-x)); }

__device__ __forceinline__ unsigned to_tf32(float v) {
    unsigned u;
    asm("cvt.rna.tf32.f32 %0, %1;" : "=r"(u) : "f"(v));
    return u;
}

__device__ __forceinline__ void mma_tf32(float* c, unsigned a0, unsigned a1,
                                         unsigned a2, unsigned a3,
                                         unsigned b0, unsigned b1) {
    asm volatile(
        "mma.sync.aligned.m16n8k8.row.col.f32.tf32.tf32.f32 "
        "{%0,%1,%2,%3}, {%4,%5,%6,%7}, {%8,%9}, {%0,%1,%2,%3};"
        : "+f"(c[0]), "+f"(c[1]), "+f"(c[2]), "+f"(c[3])
        : "r"(a0), "r"(a1), "r"(a2), "r"(a3), "r"(b0), "r"(b1));
}

__device__ __forceinline__ void cp16(uint32_t dst, const void* src, int szbytes){
    asm volatile("cp.async.cg.shared.global [%0], [%1], 16, %2;"
                 :: "r"(dst), "l"(src), "r"(szbytes));
}
__device__ __forceinline__ void cp_commit(){ asm volatile("cp.async.commit_group;"); }
__device__ __forceinline__ void cp_wait_all(){ asm volatile("cp.async.wait_all;" ::: "memory"); }

// ---------------------------------------------------------------------------
// K0: weight permute into mma-fragment order (one-time, tiny).
// dst[((chunk*9+tap)*(OC/8)+ocq)*32+lane] = {w[oc][ic0][tap], w[oc][ic1][tap]}
// with oc = ocq*8 + (lane>>2), ic0 = chunk*8 + (lane&3), ic1 = ic0+4.
// For OC=128 (fused zr): oc<64 from wA, oc>=64 from wB (index oc-64).
// ---------------------------------------------------------------------------
__global__ void wperm_k(const float* __restrict__ wA, const float* __restrict__ wB,
                        float2* __restrict__ dst, int IC, int OC, int NCHK)
{
    int i = blockIdx.x*blockDim.x + threadIdx.x;
    int total = NCHK*9*(OC/8)*32;
    if (i >= total) return;
    int lane = i & 31;
    int t1   = i >> 5;
    int ocq  = t1 % (OC/8);
    int rest = t1 / (OC/8);
    int tap  = rest % 9;
    int chunk= rest / 9;
    int gID = lane >> 2, tig = lane & 3;
    int oc  = ocq*8 + gID;
    int ic0 = chunk*8 + tig, ic1 = ic0 + 4;
    const float* wsrc = wA; int oce = oc;
    if (oc >= 64 && wB) { wsrc = wB; oce = oc - 64; }
    float v0 = (ic0 < IC) ? wsrc[((size_t)oce*IC + ic0)*9 + tap] : 0.f;
    float v1 = (ic1 < IC) ? wsrc[((size_t)oce*IC + ic1)*9 + tap] : 0.f;
    dst[i] = make_float2(__uint_as_float(to_tf32(v0)), __uint_as_float(to_tf32(v1)));
}

// ---------------------------------------------------------------------------
// K1: build hctx108 = [fR_w(64), d, sx, sy, conf, cost(40)]
// 2 threads per pixel: half 0 handles channels 0-31, half 1 handles 32-63.
// ---------------------------------------------------------------------------
__global__ void build_hctx_k(const float* __restrict__ d_, const float* __restrict__ sx,
                             const float* __restrict__ sy, const float* __restrict__ conf,
                             const float* __restrict__ fL, const float* __restrict__ fR)
{
    int idx = blockIdx.x*blockDim.x + threadIdx.x;
    if (idx >= 2*NPIX) return;
    int half = idx & 1;
    int pixi = idx >> 1;
    int w = pixi & (Wc-1);
    int h = (pixi >> 8) & (Hc-1);
    int b = pixi >> 15;
    size_t p = (size_t)h*Wc + w;
    size_t pix = (size_t)pixi;

    float d0 = d_[pix];

    int i0[Dd], i1[Dd]; float fr[Dd];
#pragma unroll
    for (int o = 0; o < Dd; o++) {
        float xs = (float)w - d0 - (float)(o - HR);
        xs = fminf(fmaxf(xs, 0.0f), (float)(Wc-1));
        float x0f = floorf(xs);
        i0[o] = (int)x0f;
        i1[o] = min(i0[o] + 1, Wc-1);
        fr[o] = xs - x0f;
    }

    size_t hb = (size_t)b * HCTX * HW;
    float cost[Dd] = {0.f,0.f,0.f,0.f,0.f};

    int c0 = half*32;
    for (int c = c0; c < c0+32; c++) {
        size_t fbase = ((size_t)(b*FC + c)) * HW;
        float fl = fL[fbase + p];
        const float* fRrow = fR + fbase + (size_t)h*Wc;
#pragma unroll
        for (int o = 0; o < Dd; o++) {
            float s = fRrow[i0[o]]*(1.0f-fr[o]) + fRrow[i1[o]]*fr[o];
            cost[o] += fl * s;
            if (o == HR) g_hctx[hb + (size_t)c*HW + p] = s;   // fR_w
        }
        if ((c & (CG-1)) == (CG-1)) {
            int g = c >> 3;
#pragma unroll
            for (int o = 0; o < Dd; o++) {
                g_hctx[hb + (size_t)(68 + g*Dd + o)*HW + p] = cost[o] * (1.0f/(float)CG);
                cost[o] = 0.f;
            }
        }
    }
    if (half == 0) {
        g_hctx[hb + (size_t)64*HW + p] = d0;
        g_hctx[hb + (size_t)65*HW + p] = sx[pix];
        g_hctx[hb + (size_t)66*HW + p] = sy[pix];
        g_hctx[hb + (size_t)67*HW + p] = conf[pix];
    }
}

// ---------------------------------------------------------------------------
// Tensor-core 3x3 conv (pad=1), implicit GEMM, tf32 mma.
// Inputs cp.async double-buffered in smem; weights read as pre-permuted
// fragments directly from global (L1/L2-resident, coalesced float2).
// Input channels resolved over up to 3 source tensors (64/64/rest split).
// MODE 0: plain   MODE 2: GRU combine (q)   MODE 4: fused z|r (OC=128)
// ---------------------------------------------------------------------------
template<int IC, int OC, int THREADS, int MODE>
__global__ void __launch_bounds__(THREADS, (THREADS==512)?1:2)
conv3x3_cp_k(const float* __restrict__ p0, int C0tot,
             const float* __restrict__ p1, int C1tot,
             const float* __restrict__ p2, int C2tot,
             const float2* __restrict__ wperm,
             const float* __restrict__ biasA, const float* __restrict__ biasB,
             float* __restrict__ out,
             const float* __restrict__ zbuf, const float* __restrict__ featbuf,
             float* __restrict__ out2)
{
    constexpr int NW   = THREADS/32;
    constexpr int OCW  = OC/(NW/4);
    constexpr int NF   = OCW/8;
    constexpr int OC8  = OC/8;
    constexpr int NCHK = (IC + 7)/8;
    constexpr int PI   = 264;            // ism row pitch (words)
    constexpr int IST  = 8*3*PI;         // ism words per stage

    extern __shared__ unsigned dsm[];
    uint32_t smem_b = (uint32_t)__cvta_generic_to_shared(dsm);

    const int tid  = threadIdx.x;
    const int lane = tid & 31;
    const int warp = tid >> 5;
    const int wm   = warp & 3;
    const int wn   = warp >> 2;
    const int h    = blockIdx.x;
    const int b    = blockIdx.y;
    const int gID  = lane >> 2;
    const int tig  = lane & 3;

    float acc[4][NF][4];
#pragma unroll
    for (int mf = 0; mf < 4; mf++)
#pragma unroll
        for (int f = 0; f < NF; f++)
#pragma unroll
            for (int j = 0; j < 4; j++) acc[mf][f][j] = 0.f;

    auto stage = [&](int chunk, int s) {
        // input: 24 row-tasks (icl 0..7, ky 0..2)
        for (int t = warp; t < 24; t += NW) {
            int icl = t / 3;
            int ky  = t - icl*3;
            int ic  = chunk*8 + icl;
            int gy  = h - 1 + ky;
            bool valid = (ic < IC) && (gy >= 0) && (gy < Hc);
            int icc = valid ? ic : 0;
            int gyc = min(max(gy, 0), Hc-1);
            const float* srcrow;
            if (icc < 64)       srcrow = p0 + (((size_t)b*C0tot + icc)*Hc + gyc)*Wc;
            else if (icc < 128) srcrow = p1 + (((size_t)b*C1tot + (icc-64))*Hc + gyc)*Wc;
            else                srcrow = p2 + (((size_t)b*C2tot + (icc-128))*Hc + gyc)*Wc;
            uint32_t dstw = smem_b + ((uint32_t)(s*IST + t*PI))*4u;
            int sz = valid ? 16 : 0;
            cp16(dstw + (4u + (uint32_t)lane*4u)*4u,      srcrow + lane*4,      sz);
            cp16(dstw + (4u + (uint32_t)(lane+32)*4u)*4u, srcrow + (lane+32)*4, sz);
            if (lane == 0) dsm[s*IST + t*PI + 3]   = 0u;   // left pad
            if (lane == 1) dsm[s*IST + t*PI + 260] = 0u;   // right pad
        }
    };

    stage(0, 0);
    cp_commit();

    for (int c = 0; c < NCHK; c++) {
        cp_wait_all();
        __syncthreads();
        if (c + 1 < NCHK) { stage(c+1, (c+1)&1); cp_commit(); }

        const unsigned* isb = dsm + (c&1)*IST;
        const float2* wcb = wperm + ((size_t)(c*9)*OC8)*32;

#pragma unroll
        for (int tap = 0; tap < 9; tap++) {
            const int ky = tap/3, kx = tap - (tap/3)*3;
            const float2* wtb = wcb + ((size_t)tap*OC8 + wn*NF)*32 + lane;
            unsigned b0[NF], b1[NF];
#pragma unroll
            for (int f = 0; f < NF; f++) {
                float2 wv = __ldg(wtb + f*32);
                b0[f] = __float_as_uint(wv.x);
                b1[f] = __float_as_uint(wv.y);
            }
            const unsigned* ib = isb + ky*PI + kx + 3;
#pragma unroll
            for (int mf = 0; mf < 4; mf++) {
                int p = wm*64 + mf*16 + gID;
                unsigned a0 = ib[ tig   *3*PI + p];
                unsigned a1 = ib[ tig   *3*PI + p + 8];
                unsigned a2 = ib[(tig+4)*3*PI + p];
                unsigned a3 = ib[(tig+4)*3*PI + p + 8];
#pragma unroll
                for (int f = 0; f < NF; f++)
                    mma_tf32(acc[mf][f], a0, a1, a2, a3, b0[f], b1[f]);
            }
        }
    }

    // ---- epilogue ----
#pragma unroll
    for (int mf = 0; mf < 4; mf++) {
#pragma unroll
        for (int f = 0; f < NF; f++) {
            int px0 = wm*64 + mf*16 + gID;
            int oc0 = wn*OCW + f*8 + 2*tig;
#pragma unroll
            for (int e = 0; e < 4; e++) {
                int px = px0 + (e >> 1)*8;
                int oc = oc0 + (e & 1);
                float val = acc[mf][f][e];
                if (MODE == 4) {
                    if (oc < 64) {
                        size_t o = (((size_t)b*64 + oc)*Hc + h)*Wc + px;
                        out[o] = sigmoidf_(val + biasA[oc]);
                    } else {
                        int oc2 = oc - 64;
                        size_t o = (((size_t)b*64 + oc2)*Hc + h)*Wc + px;
                        out2[o] = sigmoidf_(val + biasB[oc2]) * featbuf[o];
                    }
                } else {
                    size_t o = (((size_t)b*OC + oc)*Hc + h)*Wc + px;
                    if (MODE == 0) {
                        out[o] = val + (biasA ? biasA[oc] : 0.f);
                    } else { // MODE 2: GRU combine
                        float q = tanhf(val + biasA[oc]);
                        float z = zbuf[o];
                        float fv = featbuf[o];
                        float hn = (1.0f - z)*fv + z*q;
                        out[o]  = hn;
                        out2[o] = hn;
                    }
                }
            }
        }
    }
}

// ---------------------------------------------------------------------------
// GroupNorm stats: 32 blocks = (b,group), 512 threads, float4
// ---------------------------------------------------------------------------
__global__ void gn_stats_k(const float* __restrict__ x, int set)
{
    __shared__ float ss[512], ss2[512];
    int bg = blockIdx.x;
    int b  = bg >> 3, g = bg & 7;
    size_t base = ((size_t)b*HID + g*(HID/Gg)) * HW;
    const int N4 = ((HID/Gg) * HW) / 4;
    const float4* x4 = (const float4*)(x + base);
    float s = 0.f, s2 = 0.f;
    for (int i = threadIdx.x; i < N4; i += 512) {
        float4 v = x4[i];
        s  += v.x + v.y + v.z + v.w;
        s2 += v.x*v.x + v.y*v.y + v.z*v.z + v.w*v.w;
    }
    ss[threadIdx.x] = s; ss2[threadIdx.x] = s2;
    __syncthreads();
    for (int off = 256; off > 0; off >>= 1) {
        if (threadIdx.x < off) {
            ss[threadIdx.x]  += ss[threadIdx.x + off];
            ss2[threadIdx.x] += ss2[threadIdx.x + off];
        }
        __syncthreads();
    }
    if (threadIdx.x == 0) {
        const float Nf = (float)((HID/Gg)*HW);
        float mean = ss[0] / Nf;
        float var  = ss2[0] / Nf - mean*mean;
        g_gn[set*64 + bg*2]     = mean;
        g_gn[set*64 + bg*2 + 1] = rsqrtf(var + 1e-5f);
    }
}

// ---------------------------------------------------------------------------
// GroupNorm apply + SiLU (float4)
// ---------------------------------------------------------------------------
__global__ void gn_apply_k(const float* __restrict__ x, float* __restrict__ y,
                           const float* __restrict__ scale, const float* __restrict__ bias,
                           int set)
{
    int i4 = blockIdx.x*blockDim.x + threadIdx.x;
    const int n4 = (Bn*HID*HW)/4;
    if (i4 >= n4) return;
    int i = i4*4;
    int c = (i / HW) % HID;
    int b = i / (HID*HW);
    int grp = c / (HID/Gg);
    float mean = g_gn[set*64 + (b*8+grp)*2];
    float rstd = g_gn[set*64 + (b*8+grp)*2 + 1];
    float sc = scale[c]*rstd, bi = bias[c] - mean*rstd*scale[c];
    float4 v = ((const float4*)x)[i4];
    float4 o;
    float t;
    t = v.x*sc + bi; o.x = t * sigmoidf_(t);
    t = v.y*sc + bi; o.y = t * sigmoidf_(t);
    t = v.z*sc + bi; o.z = t * sigmoidf_(t);
    t = v.w*sc + bi; o.w = t * sigmoidf_(t);
    ((float4*)y)[i4] = o;
}

// ---------------------------------------------------------------------------
// Heads: fused GN2-apply + SiLU + four 1x1 convs (48->1) + activations.
// ---------------------------------------------------------------------------
__global__ void heads_k(const float* __restrict__ t,
                        const float* __restrict__ gnsc, const float* __restrict__ gnbi,
                        const float* __restrict__ d_, const float* __restrict__ sx,
                        const float* __restrict__ sy, const float* __restrict__ conf,
                        const float* __restrict__ wd,  const float* __restrict__ bd,
                        const float* __restrict__ wsx, const float* __restrict__ bsx,
                        const float* __restrict__ wsy, const float* __restrict__ bsy,
                        const float* __restrict__ wcf, const float* __restrict__ bcf,
                        float* __restrict__ out)
{
    __shared__ float wsm[4][HID];
    __shared__ float csc[HID], cbi[HID];
    int tid = threadIdx.x;
    if (tid < HID)              wsm[0][tid]        = wd [tid];
    else if (tid < 2*HID)       wsm[1][tid-HID]    = wsx[tid-HID];
    else if (tid < 3*HID)       wsm[2][tid-2*HID]  = wsy[tid-2*HID];
    else if (tid < 4*HID)       wsm[3][tid-3*HID]  = wcf[tid-3*HID];
    if (tid < HID) { csc[tid] = gnsc[tid]; cbi[tid] = gnbi[tid]; }
    __syncthreads();

    int idx = blockIdx.x*blockDim.x + tid;
    if (idx >= NPIX) return;
    int b = idx >> 15;
    size_t p = (size_t)(idx & (HW-1));
    size_t pix = (size_t)idx;

    float gmean[8], grstd[8];
#pragma unroll
    for (int g = 0; g < 8; g++) {
        gmean[g] = g_gn[64 + (b*8+g)*2];
        grstd[g] = g_gn[64 + (b*8+g)*2 + 1];
    }

    float a0=0.f, a1=0.f, a2=0.f, a3=0.f;
    size_t base = (size_t)b*HID*HW + p;
#pragma unroll
    for (int c = 0; c < HID; c++) {
        int g = c / (HID/Gg);
        float v = (t[base + (size_t)c*HW] - gmean[g])*grstd[g]*csc[c] + cbi[c];
        v = v * sigmoidf_(v);
        a0 = fmaf(v, wsm[0][c], a0);
        a1 = fmaf(v, wsm[1][c], a1);
        a2 = fmaf(v, wsm[2][c], a2);
        a3 = fmaf(v, wsm[3][c], a3);
    }
    float ad = a0 + bd[0] + d_[pix];
    out[O_D + pix]  = (ad > 20.0f) ? ad : log1pf(expf(ad));
    out[O_SX + pix] = sx[pix] + (a1 + bsx[0]) * 0.1f;
    out[O_SY + pix] = sy[pix] + (a2 + bsy[0]) * 0.1f;
    out[O_CONF + pix] = sigmoidf_(a3 + bcf[0] + 2.0f*conf[pix] - 1.0f);
}

// ---------------------------------------------------------------------------
extern "C" void kernel_launch(void* const* d_in, const int* in_sizes, int n_in,
                              void* d_out, int out_size)
{
    const float* d_   = (const float*)d_in[0];
    const float* sx   = (const float*)d_in[1];
    const float* sy   = (const float*)d_in[2];
    const float* conf = (const float*)d_in[3];
    const float* feat = (const float*)d_in[4];
    const float* fL   = (const float*)d_in[5];
    const float* fR   = (const float*)d_in[6];
    const float* wz   = (const float*)d_in[7];
    const float* bz   = (const float*)d_in[8];
    const float* wr   = (const float*)d_in[9];
    const float* br   = (const float*)d_in[10];
    const float* wq   = (const float*)d_in[11];
    const float* bq   = (const float*)d_in[12];
    const float* w1   = (const float*)d_in[13];
    const float* g1s  = (const float*)d_in[14];
    const float* g1b  = (const float*)d_in[15];
    const float* w2   = (const float*)d_in[16];
    const float* g2s  = (const float*)d_in[17];
    const float* g2b  = (const float*)d_in[18];
    const float* whd  = (const float*)d_in[19];
    const float* bhd  = (const float*)d_in[20];
    const float* whx  = (const float*)d_in[21];
    const float* bhx  = (const float*)d_in[22];
    const float* why  = (const float*)d_in[23];
    const float* bhy  = (const float*)d_in[24];
    const float* whc  = (const float*)d_in[25];
    const float* bhc  = (const float*)d_in[26];
    float* out = (float*)d_out;

    float *hctx, *z, *r, *hnew, *ta, *tb;
    float2 *wzr, *wqp, *wt1, *wt2;
    cudaGetSymbolAddress((void**)&hctx, g_hctx);
    cudaGetSymbolAddress((void**)&z,    g_z);
    cudaGetSymbolAddress((void**)&r,    g_r);
    cudaGetSymbolAddress((void**)&hnew, g_hnew);
    cudaGetSymbolAddress((void**)&ta,   g_ta);
    cudaGetSymbolAddress((void**)&tb,   g_tb);
    cudaGetSymbolAddress((void**)&wzr,  g_wzr);
    cudaGetSymbolAddress((void**)&wqp,  g_wq);
    cudaGetSymbolAddress((void**)&wt1,  g_wt1);
    cudaGetSymbolAddress((void**)&wt2,  g_wt2);

    const int SM_I = 2*(8*3*264)*4;     // 50688 bytes (2 input stages)

    cudaFuncSetAttribute(conv3x3_cp_k<GRU_IN,128,512,4>,
                         cudaFuncAttributeMaxDynamicSharedMemorySize, SM_I);
    cudaFuncSetAttribute(conv3x3_cp_k<GRU_IN,64,256,2>,
                         cudaFuncAttributeMaxDynamicSharedMemorySize, SM_I);
    cudaFuncSetAttribute(conv3x3_cp_k<TC,HID,256,0>,
                         cudaFuncAttributeMaxDynamicSharedMemorySize, SM_I);
    cudaFuncSetAttribute(conv3x3_cp_k<HID,HID,256,0>,
                         cudaFuncAttributeMaxDynamicSharedMemorySize, SM_I);

    // One-time weight permutes (cheap; graph replays them harmlessly)
    {
        int n;
        n = 30*9*16*32; wperm_k<<<(n+255)/256,256>>>(wz, wr, wzr, GRU_IN, 128, 30);
        n = 30*9* 8*32; wperm_k<<<(n+255)/256,256>>>(wq, nullptr, wqp, GRU_IN, 64, 30);
        n =  8*9* 6*32; wperm_k<<<(n+255)/256,256>>>(w1, nullptr, wt1, TC,  HID,  8);
        n =  6*9* 6*32; wperm_k<<<(n+255)/256,256>>>(w2, nullptr, wt2, HID, HID,  6);
    }

    dim3 cgrid(Hc, Bn);

    build_hctx_k<<<(2*NPIX)/256, 256>>>(d_, sx, sy, conf, fL, fR);

    // fused z|r conv: z = sigmoid(conv_z); r*feat = sigmoid(conv_r)*feat
    // sources: feat(0-63) | fL(64-127) | hctx108(128-235)
    conv3x3_cp_k<GRU_IN,128,512,4><<<cgrid, 512, SM_I>>>(
        feat, 64, fL, 64, hctx, HCTX,
        wzr, bz, br, z, nullptr, feat, r);

    // q conv + GRU combine -> hnew (and output h slot)
    conv3x3_cp_k<GRU_IN,64,256,2><<<cgrid, 256, SM_I>>>(
        r, 64, fL, 64, hctx, HCTX,
        wqp, bq, nullptr, hnew, z, feat, out + O_H);

    conv3x3_cp_k<TC,HID,256,0><<<cgrid, 256, SM_I>>>(
        hnew, TC, hnew, TC, hnew, TC,
        wt1, nullptr, nullptr, ta, nullptr, nullptr, nullptr);
    gn_stats_k<<<32, 512>>>(ta, 0);
    gn_apply_k<<<(Bn*HID*HW)/4/256, 256>>>(ta, tb, g1s, g1b, 0);

    conv3x3_cp_k<HID,HID,256,0><<<cgrid, 256, SM_I>>>(
        tb, HID, tb, HID, tb, HID,
        wt2, nullptr, nullptr, ta, nullptr, nullptr, nullptr);
    gn_stats_k<<<32, 512>>>(ta, 1);

    // heads with fused GN2 apply + SiLU
    heads_k<<<NPIX/256, 256>>>(ta, g2s, g2b, d_, sx, sy, conf,
                               whd, bhd, whx, bhx, why, bhy, whc, bhc, out);
}

// round 11
// speedup vs baseline: 5.7988x; 1.0436x over previous
#include <cuda_runtime.h>
#include <cuda_bf16.h>
#include <math.h>
#include <stdint.h>

// Problem constants
#define Bn 4
#define FC 64
#define TC 64
#define HID 48
#define HR 2
#define Gg 8
#define Hc 128
#define Wc 256
#define Dd 5
#define CG 8
#define GRU_IN 236
#define HCTX 108
#define HW (Hc*Wc)            // 32768
#define NPIX (Bn*HW)          // 131072

// Output layout (flattened tuple in return order)
#define O_D    0
#define O_SX   (NPIX)
#define O_SY   (2*NPIX)
#define O_H    (3*NPIX)
#define O_CONF (3*NPIX + Bn*TC*HW)

// Scratch (device globals; no allocation allowed)
__device__ float g_hctx[(size_t)Bn*HCTX*HW];     // [fR_w(64), d,sx,sy,conf(4), cost(40)]
__device__ float g_z  [(size_t)Bn*TC*HW];
__device__ float g_r  [(size_t)Bn*TC*HW];        // holds r*feat (fused)
__device__ float g_hnew[(size_t)Bn*TC*HW];
__device__ float g_ta [(size_t)Bn*HID*HW];
__device__ float g_tb [(size_t)Bn*HID*HW];
__device__ float g_gnsum[128];                   // 2 sets x 32 (b,g) x {sum,sum2}

// Fragment-permuted tf32 weights: [chunk][tap][ocq][lane] -> float2 {b0,b1}
__device__ float2 g_wzr[30*9*16*32];   // z|r fused, OC=128
__device__ float2 g_wq [30*9* 8*32];   // q, OC=64
__device__ float2 g_wt1[ 8*9* 6*32];   // trunk1, IC=64, OC=48
__device__ float2 g_wt2[ 6*9* 6*32];   // trunk2, IC=48, OC=48

#define GN_N ((HID/Gg)*HW)     // elements per (b,group) = 196608

// ---- fast transcendentals (MUFU-based) ----
__device__ __forceinline__ float fsig(float x){
    return __fdividef(1.0f, 1.0f + __expf(-x));
}
__device__ __forceinline__ float ftanh(float x){
    float xc = fminf(fmaxf(x, -15.0f), 15.0f);
    float e  = __expf(2.0f*xc);
    return __fdividef(e - 1.0f, e + 1.0f);
}
__device__ __forceinline__ float fsoftplus(float x){
    return (x > 20.0f) ? x : __logf(1.0f + __expf(x));
}

__device__ __forceinline__ unsigned to_tf32(float v) {
    unsigned u;
    asm("cvt.rna.tf32.f32 %0, %1;" : "=r"(u) : "f"(v));
    return u;
}

__device__ __forceinline__ void mma_tf32(float* c, unsigned a0, unsigned a1,
                                         unsigned a2, unsigned a3,
                                         unsigned b0, unsigned b1) {
    asm volatile(
        "mma.sync.aligned.m16n8k8.row.col.f32.tf32.tf32.f32 "
        "{%0,%1,%2,%3}, {%4,%5,%6,%7}, {%8,%9}, {%0,%1,%2,%3};"
        : "+f"(c[0]), "+f"(c[1]), "+f"(c[2]), "+f"(c[3])
        : "r"(a0), "r"(a1), "r"(a2), "r"(a3), "r"(b0), "r"(b1));
}

__device__ __forceinline__ void cp16(uint32_t dst, const void* src, int szbytes){
    asm volatile("cp.async.cg.shared.global [%0], [%1], 16, %2;"
                 :: "r"(dst), "l"(src), "r"(szbytes));
}
__device__ __forceinline__ void cp_commit(){ asm volatile("cp.async.commit_group;"); }
__device__ __forceinline__ void cp_wait_all(){ asm volatile("cp.async.wait_all;" ::: "memory"); }

// ---------------------------------------------------------------------------
// K0: ALL weight permutes in one launch + zero gn accumulator.
// Segment layout identical to wperm_k of round 9 per conv.
// ---------------------------------------------------------------------------
__device__ __forceinline__ void wperm_one(const float* wA, const float* wB,
                                          float2* dst, int IC, int OC, int i)
{
    int lane = i & 31;
    int t1   = i >> 5;
    int ocq  = t1 % (OC/8);
    int rest = t1 / (OC/8);
    int tap  = rest % 9;
    int chunk= rest / 9;
    int gID = lane >> 2, tig = lane & 3;
    int oc  = ocq*8 + gID;
    int ic0 = chunk*8 + tig, ic1 = ic0 + 4;
    const float* wsrc = wA; int oce = oc;
    if (oc >= 64 && wB) { wsrc = wB; oce = oc - 64; }
    float v0 = (ic0 < IC) ? wsrc[((size_t)oce*IC + ic0)*9 + tap] : 0.f;
    float v1 = (ic1 < IC) ? wsrc[((size_t)oce*IC + ic1)*9 + tap] : 0.f;
    dst[i] = make_float2(__uint_as_float(to_tf32(v0)), __uint_as_float(to_tf32(v1)));
}

#define NZR (30*9*16*32)
#define NQ  (30*9*8*32)
#define NT1 (8*9*6*32)
#define NT2 (6*9*6*32)

__global__ void wperm_all_k(const float* __restrict__ wz, const float* __restrict__ wr,
                            const float* __restrict__ wq, const float* __restrict__ w1,
                            const float* __restrict__ w2)
{
    int i = blockIdx.x*blockDim.x + threadIdx.x;
    if (i < 128) g_gnsum[i] = 0.f;
    if (i < NZR) { wperm_one(wz, wr, g_wzr, GRU_IN, 128, i); return; }
    i -= NZR;
    if (i < NQ)  { wperm_one(wq, nullptr, g_wq, GRU_IN, 64, i); return; }
    i -= NQ;
    if (i < NT1) { wperm_one(w1, nullptr, g_wt1, TC, HID, i); return; }
    i -= NT1;
    if (i < NT2) { wperm_one(w2, nullptr, g_wt2, HID, HID, i); return; }
}

// ---------------------------------------------------------------------------
// K1: build hctx108 = [fR_w(64), d, sx, sy, conf, cost(40)]
// 4 threads per pixel: quarter q handles channels q*16 .. q*16+15.
// ---------------------------------------------------------------------------
__global__ void build_hctx_k(const float* __restrict__ d_, const float* __restrict__ sx,
                             const float* __restrict__ sy, const float* __restrict__ conf,
                             const float* __restrict__ fL, const float* __restrict__ fR)
{
    int idx = blockIdx.x*blockDim.x + threadIdx.x;
    if (idx >= 4*NPIX) return;
    int quarter = idx & 3;
    int pixi = idx >> 2;
    int w = pixi & (Wc-1);
    int h = (pixi >> 8) & (Hc-1);
    int b = pixi >> 15;
    size_t p = (size_t)h*Wc + w;
    size_t pix = (size_t)pixi;

    float d0 = d_[pix];

    int i0[Dd], i1[Dd]; float fr[Dd];
#pragma unroll
    for (int o = 0; o < Dd; o++) {
        float xs = (float)w - d0 - (float)(o - HR);
        xs = fminf(fmaxf(xs, 0.0f), (float)(Wc-1));
        float x0f = floorf(xs);
        i0[o] = (int)x0f;
        i1[o] = min(i0[o] + 1, Wc-1);
        fr[o] = xs - x0f;
    }

    size_t hb = (size_t)b * HCTX * HW;
    float cost[Dd] = {0.f,0.f,0.f,0.f,0.f};

    int c0 = quarter*16;
    for (int c = c0; c < c0+16; c++) {
        size_t fbase = ((size_t)(b*FC + c)) * HW;
        float fl = __ldg(fL + fbase + p);
        const float* fRrow = fR + fbase + (size_t)h*Wc;
#pragma unroll
        for (int o = 0; o < Dd; o++) {
            float s = __ldg(fRrow + i0[o])*(1.0f-fr[o]) + __ldg(fRrow + i1[o])*fr[o];
            cost[o] += fl * s;
            if (o == HR) g_hctx[hb + (size_t)c*HW + p] = s;   // fR_w
        }
        if ((c & (CG-1)) == (CG-1)) {
            int g = c >> 3;
#pragma unroll
            for (int o = 0; o < Dd; o++) {
                g_hctx[hb + (size_t)(68 + g*Dd + o)*HW + p] = cost[o] * (1.0f/(float)CG);
                cost[o] = 0.f;
            }
        }
    }
    if (quarter == 0) {
        g_hctx[hb + (size_t)64*HW + p] = d0;
        g_hctx[hb + (size_t)65*HW + p] = sx[pix];
        g_hctx[hb + (size_t)66*HW + p] = sy[pix];
        g_hctx[hb + (size_t)67*HW + p] = conf[pix];
    }
}

// ---------------------------------------------------------------------------
// Tensor-core 3x3 conv (pad=1), implicit GEMM, tf32 mma.
// Inputs cp.async double-buffered in smem; weights read as pre-permuted
// fragments directly from global (L1/L2-resident, coalesced float2).
// MODE 0: plain   MODE 2: GRU combine (q)   MODE 4: fused z|r (OC=128)
// ---------------------------------------------------------------------------
template<int IC, int OC, int THREADS, int MODE>
__global__ void __launch_bounds__(THREADS, (THREADS==512)?1:2)
conv3x3_cp_k(const float* __restrict__ p0, int C0tot,
             const float* __restrict__ p1, int C1tot,
             const float* __restrict__ p2, int C2tot,
             const float2* __restrict__ wperm,
             const float* __restrict__ biasA, const float* __restrict__ biasB,
             float* __restrict__ out,
             const float* __restrict__ zbuf, const float* __restrict__ featbuf,
             float* __restrict__ out2)
{
    constexpr int NW   = THREADS/32;
    constexpr int OCW  = OC/(NW/4);
    constexpr int NF   = OCW/8;
    constexpr int OC8  = OC/8;
    constexpr int NCHK = (IC + 7)/8;
    constexpr int PI   = 264;            // ism row pitch (words)
    constexpr int IST  = 8*3*PI;         // ism words per stage

    extern __shared__ unsigned dsm[];
    uint32_t smem_b = (uint32_t)__cvta_generic_to_shared(dsm);

    const int tid  = threadIdx.x;
    const int lane = tid & 31;
    const int warp = tid >> 5;
    const int wm   = warp & 3;
    const int wn   = warp >> 2;
    const int h    = blockIdx.x;
    const int b    = blockIdx.y;
    const int gID  = lane >> 2;
    const int tig  = lane & 3;

    float acc[4][NF][4];
#pragma unroll
    for (int mf = 0; mf < 4; mf++)
#pragma unroll
        for (int f = 0; f < NF; f++)
#pragma unroll
            for (int j = 0; j < 4; j++) acc[mf][f][j] = 0.f;

    auto stage = [&](int chunk, int s) {
        for (int t = warp; t < 24; t += NW) {
            int icl = t / 3;
            int ky  = t - icl*3;
            int ic  = chunk*8 + icl;
            int gy  = h - 1 + ky;
            bool valid = (ic < IC) && (gy >= 0) && (gy < Hc);
            int icc = valid ? ic : 0;
            int gyc = min(max(gy, 0), Hc-1);
            const float* srcrow;
            if (icc < 64)       srcrow = p0 + (((size_t)b*C0tot + icc)*Hc + gyc)*Wc;
            else if (icc < 128) srcrow = p1 + (((size_t)b*C1tot + (icc-64))*Hc + gyc)*Wc;
            else                srcrow = p2 + (((size_t)b*C2tot + (icc-128))*Hc + gyc)*Wc;
            uint32_t dstw = smem_b + ((uint32_t)(s*IST + t*PI))*4u;
            int sz = valid ? 16 : 0;
            cp16(dstw + (4u + (uint32_t)lane*4u)*4u,      srcrow + lane*4,      sz);
            cp16(dstw + (4u + (uint32_t)(lane+32)*4u)*4u, srcrow + (lane+32)*4, sz);
            if (lane == 0) dsm[s*IST + t*PI + 3]   = 0u;   // left pad
            if (lane == 1) dsm[s*IST + t*PI + 260] = 0u;   // right pad
        }
    };

    stage(0, 0);
    cp_commit();

    for (int c = 0; c < NCHK; c++) {
        cp_wait_all();
        __syncthreads();
        if (c + 1 < NCHK) { stage(c+1, (c+1)&1); cp_commit(); }

        const unsigned* isb = dsm + (c&1)*IST;
        const float2* wcb = wperm + ((size_t)(c*9)*OC8)*32;

#pragma unroll
        for (int tap = 0; tap < 9; tap++) {
            const int ky = tap/3, kx = tap - (tap/3)*3;
            const float2* wtb = wcb + ((size_t)tap*OC8 + wn*NF)*32 + lane;
            unsigned b0[NF], b1[NF];
#pragma unroll
            for (int f = 0; f < NF; f++) {
                float2 wv = __ldg(wtb + f*32);
                b0[f] = __float_as_uint(wv.x);
                b1[f] = __float_as_uint(wv.y);
            }
            const unsigned* ib = isb + ky*PI + kx + 3;
#pragma unroll
            for (int mf = 0; mf < 4; mf++) {
                int p = wm*64 + mf*16 + gID;
                unsigned a0 = ib[ tig   *3*PI + p];
                unsigned a1 = ib[ tig   *3*PI + p + 8];
                unsigned a2 = ib[(tig+4)*3*PI + p];
                unsigned a3 = ib[(tig+4)*3*PI + p + 8];
#pragma unroll
                for (int f = 0; f < NF; f++)
                    mma_tf32(acc[mf][f], a0, a1, a2, a3, b0[f], b1[f]);
            }
        }
    }

    // ---- epilogue ----
#pragma unroll
    for (int mf = 0; mf < 4; mf++) {
#pragma unroll
        for (int f = 0; f < NF; f++) {
            int px0 = wm*64 + mf*16 + gID;
            int oc0 = wn*OCW + f*8 + 2*tig;
#pragma unroll
            for (int e = 0; e < 4; e++) {
                int px = px0 + (e >> 1)*8;
                int oc = oc0 + (e & 1);
                float val = acc[mf][f][e];
                if (MODE == 4) {
                    if (oc < 64) {
                        size_t o = (((size_t)b*64 + oc)*Hc + h)*Wc + px;
                        out[o] = fsig(val + biasA[oc]);
                    } else {
                        int oc2 = oc - 64;
                        size_t o = (((size_t)b*64 + oc2)*Hc + h)*Wc + px;
                        out2[o] = fsig(val + biasB[oc2]) * featbuf[o];
                    }
                } else {
                    size_t o = (((size_t)b*OC + oc)*Hc + h)*Wc + px;
                    if (MODE == 0) {
                        out[o] = val + (biasA ? biasA[oc] : 0.f);
                    } else { // MODE 2: GRU combine
                        float q = ftanh(val + biasA[oc]);
                        float z = zbuf[o];
                        float fv = featbuf[o];
                        float hn = (1.0f - z)*fv + z*q;
                        out[o]  = hn;
                        out2[o] = hn;
                    }
                }
            }
        }
    }
}

// ---------------------------------------------------------------------------
// GroupNorm partial stats: 256 blocks = (b,group) x 8 slices; atomicAdd sums.
// ---------------------------------------------------------------------------
__global__ void gn_statsp_k(const float* __restrict__ x, int set)
{
    __shared__ float ss[256], ss2[256];
    int bg    = blockIdx.x >> 3;
    int slice = blockIdx.x & 7;
    int b  = bg >> 3, g = bg & 7;
    size_t base = ((size_t)b*HID + g*(HID/Gg)) * HW + (size_t)slice*(GN_N/8);
    const int N4 = (GN_N/8)/4;   // 6144 float4 per slice
    const float4* x4 = (const float4*)(x + base);
    float s = 0.f, s2 = 0.f;
    for (int i = threadIdx.x; i < N4; i += 256) {
        float4 v = x4[i];
        s  += v.x + v.y + v.z + v.w;
        s2 += v.x*v.x + v.y*v.y + v.z*v.z + v.w*v.w;
    }
    ss[threadIdx.x] = s; ss2[threadIdx.x] = s2;
    __syncthreads();
    for (int off = 128; off > 0; off >>= 1) {
        if (threadIdx.x < off) {
            ss[threadIdx.x]  += ss[threadIdx.x + off];
            ss2[threadIdx.x] += ss2[threadIdx.x + off];
        }
        __syncthreads();
    }
    if (threadIdx.x == 0) {
        atomicAdd(&g_gnsum[set*64 + bg*2],     ss[0]);
        atomicAdd(&g_gnsum[set*64 + bg*2 + 1], ss2[0]);
    }
}

__device__ __forceinline__ void gn_mr(int set, int bg, float& mean, float& rstd)
{
    float s  = g_gnsum[set*64 + bg*2];
    float s2 = g_gnsum[set*64 + bg*2 + 1];
    mean = s * (1.0f/(float)GN_N);
    float var = s2 * (1.0f/(float)GN_N) - mean*mean;
    rstd = rsqrtf(var + 1e-5f);
}

// ---------------------------------------------------------------------------
// GroupNorm apply + SiLU (float4)
// ---------------------------------------------------------------------------
__global__ void gn_apply_k(const float* __restrict__ x, float* __restrict__ y,
                           const float* __restrict__ scale, const float* __restrict__ bias,
                           int set)
{
    int i4 = blockIdx.x*blockDim.x + threadIdx.x;
    const int n4 = (Bn*HID*HW)/4;
    if (i4 >= n4) return;
    int i = i4*4;
    int c = (i / HW) % HID;
    int b = i / (HID*HW);
    int grp = c / (HID/Gg);
    float mean, rstd;
    gn_mr(set, b*8+grp, mean, rstd);
    float sc = scale[c]*rstd, bi = bias[c] - mean*rstd*scale[c];
    float4 v = ((const float4*)x)[i4];
    float4 o;
    float t;
    t = v.x*sc + bi; o.x = t * fsig(t);
    t = v.y*sc + bi; o.y = t * fsig(t);
    t = v.z*sc + bi; o.z = t * fsig(t);
    t = v.w*sc + bi; o.w = t * fsig(t);
    ((float4*)y)[i4] = o;
}

// ---------------------------------------------------------------------------
// Heads: fused GN2-apply + SiLU + four 1x1 convs (48->1) + activations.
// ---------------------------------------------------------------------------
__global__ void heads_k(const float* __restrict__ t,
                        const float* __restrict__ gnsc, const float* __restrict__ gnbi,
                        const float* __restrict__ d_, const float* __restrict__ sx,
                        const float* __restrict__ sy, const float* __restrict__ conf,
                        const float* __restrict__ wd,  const float* __restrict__ bd,
                        const float* __restrict__ wsx, const float* __restrict__ bsx,
                        const float* __restrict__ wsy, const float* __restrict__ bsy,
                        const float* __restrict__ wcf, const float* __restrict__ bcf,
                        float* __restrict__ out)
{
    __shared__ float wsm[4][HID];
    __shared__ float csc[HID], cbi[HID];
    int tid = threadIdx.x;
    if (tid < HID)              wsm[0][tid]        = wd [tid];
    else if (tid < 2*HID)       wsm[1][tid-HID]    = wsx[tid-HID];
    else if (tid < 3*HID)       wsm[2][tid-2*HID]  = wsy[tid-2*HID];
    else if (tid < 4*HID)       wsm[3][tid-3*HID]  = wcf[tid-3*HID];
    if (tid < HID) { csc[tid] = gnsc[tid]; cbi[tid] = gnbi[tid]; }
    __syncthreads();

    int idx = blockIdx.x*blockDim.x + tid;
    if (idx >= NPIX) return;
    int b = idx >> 15;
    size_t p = (size_t)(idx & (HW-1));
    size_t pix = (size_t)idx;

    float gmean[8], grstd[8];
#pragma unroll
    for (int g = 0; g < 8; g++) gn_mr(1, b*8+g, gmean[g], grstd[g]);

    float a0=0.f, a1=0.f, a2=0.f, a3=0.f;
    size_t base = (size_t)b*HID*HW + p;
#pragma unroll
    for (int c = 0; c < HID; c++) {
        int g = c / (HID/Gg);
        float v = (t[base + (size_t)c*HW] - gmean[g])*grstd[g]*csc[c] + cbi[c];
        v = v * fsig(v);
        a0 = fmaf(v, wsm[0][c], a0);
        a1 = fmaf(v, wsm[1][c], a1);
        a2 = fmaf(v, wsm[2][c], a2);
        a3 = fmaf(v, wsm[3][c], a3);
    }
    float ad = a0 + bd[0] + d_[pix];
    out[O_D + pix]  = fsoftplus(ad);
    out[O_SX + pix] = sx[pix] + (a1 + bsx[0]) * 0.1f;
    out[O_SY + pix] = sy[pix] + (a2 + bsy[0]) * 0.1f;
    out[O_CONF + pix] = fsig(a3 + bcf[0] + 2.0f*conf[pix] - 1.0f);
}

// ---------------------------------------------------------------------------
extern "C" void kernel_launch(void* const* d_in, const int* in_sizes, int n_in,
                              void* d_out, int out_size)
{
    const float* d_   = (const float*)d_in[0];
    const float* sx   = (const float*)d_in[1];
    const float* sy   = (const float*)d_in[2];
    const float* conf = (const float*)d_in[3];
    const float* feat = (const float*)d_in[4];
    const float* fL   = (const float*)d_in[5];
    const float* fR   = (const float*)d_in[6];
    const float* wz   = (const float*)d_in[7];
    const float* bz   = (const float*)d_in[8];
    const float* wr   = (const float*)d_in[9];
    const float* br   = (const float*)d_in[10];
    const float* wq   = (const float*)d_in[11];
    const float* bq   = (const float*)d_in[12];
    const float* w1   = (const float*)d_in[13];
    const float* g1s  = (const float*)d_in[14];
    const float* g1b  = (const float*)d_in[15];
    const float* w2   = (const float*)d_in[16];
    const float* g2s  = (const float*)d_in[17];
    const float* g2b  = (const float*)d_in[18];
    const float* whd  = (const float*)d_in[19];
    const float* bhd  = (const float*)d_in[20];
    const float* whx  = (const float*)d_in[21];
    const float* bhx  = (const float*)d_in[22];
    const float* why  = (const float*)d_in[23];
    const float* bhy  = (const float*)d_in[24];
    const float* whc  = (const float*)d_in[25];
    const float* bhc  = (const float*)d_in[26];
    float* out = (float*)d_out;

    float *hctx, *z, *r, *hnew, *ta, *tb;
    float2 *wzr, *wqp, *wt1, *wt2;
    cudaGetSymbolAddress((void**)&hctx, g_hctx);
    cudaGetSymbolAddress((void**)&z,    g_z);
    cudaGetSymbolAddress((void**)&r,    g_r);
    cudaGetSymbolAddress((void**)&hnew, g_hnew);
    cudaGetSymbolAddress((void**)&ta,   g_ta);
    cudaGetSymbolAddress((void**)&tb,   g_tb);
    cudaGetSymbolAddress((void**)&wzr,  g_wzr);
    cudaGetSymbolAddress((void**)&wqp,  g_wq);
    cudaGetSymbolAddress((void**)&wt1,  g_wt1);
    cudaGetSymbolAddress((void**)&wt2,  g_wt2);

    const int SM_I = 2*(8*3*264)*4;     // 50688 bytes (2 input stages)

    cudaFuncSetAttribute(conv3x3_cp_k<GRU_IN,128,512,4>,
                         cudaFuncAttributeMaxDynamicSharedMemorySize, SM_I);
    cudaFuncSetAttribute(conv3x3_cp_k<GRU_IN,64,256,2>,
                         cudaFuncAttributeMaxDynamicSharedMemorySize, SM_I);
    cudaFuncSetAttribute(conv3x3_cp_k<TC,HID,256,0>,
                         cudaFuncAttributeMaxDynamicSharedMemorySize, SM_I);
    cudaFuncSetAttribute(conv3x3_cp_k<HID,HID,256,0>,
                         cudaFuncAttributeMaxDynamicSharedMemorySize, SM_I);

    // One-time weight permutes + gnsum zero (single launch)
    {
        int total = NZR + NQ + NT1 + NT2;
        wperm_all_k<<<(total+255)/256, 256>>>(wz, wr, wq, w1, w2);
    }

    dim3 cgrid(Hc, Bn);

    build_hctx_k<<<(4*NPIX)/256, 256>>>(d_, sx, sy, conf, fL, fR);

    // fused z|r conv: z = sigmoid(conv_z); r*feat = sigmoid(conv_r)*feat
    // sources: feat(0-63) | fL(64-127) | hctx108(128-235)
    conv3x3_cp_k<GRU_IN,128,512,4><<<cgrid, 512, SM_I>>>(
        feat, 64, fL, 64, hctx, HCTX,
        wzr, bz, br, z, nullptr, feat, r);

    // q conv + GRU combine -> hnew (and output h slot)
    conv3x3_cp_k<GRU_IN,64,256,2><<<cgrid, 256, SM_I>>>(
        r, 64, fL, 64, hctx, HCTX,
        wqp, bq, nullptr, hnew, z, feat, out + O_H);

    conv3x3_cp_k<TC,HID,256,0><<<cgrid, 256, SM_I>>>(
        hnew, TC, hnew, TC, hnew, TC,
        wt1, nullptr, nullptr, ta, nullptr, nullptr, nullptr);
    gn_statsp_k<<<256, 256>>>(ta, 0);
    gn_apply_k<<<(Bn*HID*HW)/4/256, 256>>>(ta, tb, g1s, g1b, 0);

    conv3x3_cp_k<HID,HID,256,0><<<cgrid, 256, SM_I>>>(
        tb, HID, tb, HID, tb, HID,
        wt2, nullptr, nullptr, ta, nullptr, nullptr, nullptr);
    gn_statsp_k<<<256, 256>>>(ta, 1);

    // heads with fused GN2 apply + SiLU
    heads_k<<<NPIX/256, 256>>>(ta, g2s, g2b, d_, sx, sy, conf,
                               whd, bhd, whx, bhx, why, bhy, whc, bhc, out);
}